// round 13
// baseline (speedup 1.0000x reference)
#include <cuda_runtime.h>
#include <cstdint>

#define BATCH 2
#define TT 512
#define DM 768
#define DI 1536
#define DS 16
#define NROW (BATCH*TT)          // 1024
#define KCONV 4
#define KW (KCONV*DI)            // 6144
#define ND (DS*DI)               // 24576
#define CH 64
#define NCHUNK (TT/CH)           // 8
#define SCTH 128                 // scan threads: 8 dl x 16 n; 128 hist columns/block

typedef unsigned long long u64;
static __device__ __forceinline__ void ffma2(u64& d, u64 a, u64 b){
    asm("fma.rn.f32x2 %0, %1, %2, %0;" : "+l"(d) : "l"(a), "l"(b));
}
static __device__ __forceinline__ u64 pack2(float x, float y){
    u64 r; asm("mov.b64 %0, {%1, %2};" : "=l"(r) : "f"(x), "f"(y)); return r;
}
static __device__ __forceinline__ void unpack2(u64 v, float& x, float& y){
    asm("mov.b64 {%0, %1}, %2;" : "=f"(x), "=f"(y) : "l"(v));
}
#define ONE2 0x3f8000003f800000ull

// scan dynamic smem (floats)
#define LH_F    (CH*SCTH)        // 8192
#define WFP_F   (2048)           // u64 wfp[16][64] = 2048 float-equivalents
#define STAGE_F (16*SCTH)        // 2048
#define SXS_F   (CH*33)          // 2112
#define SXA_F   (CH*8)           // 512
#define SXZ_F   (CH*8)           // 512
#define SCAN_DYN ((LH_F+WFP_F+STAGE_F+SXS_F+SXA_F+SXZ_F)*sizeof(float))

// ---------------- scratch ----------------
__device__ __align__(16) float g_xn   [NROW*DM];
__device__ __align__(16) float g_xz   [NROW*2*DI];
__device__ __align__(16) float g_xact [NROW*DI];
__device__ __align__(16) float g_wc   [DI*KW];
__device__ __align__(16) float g_xssm [NROW*33];
__device__ __align__(16) float g_hist [(size_t)BATCH*TT*ND];   // block-local cols
__device__ __align__(16) float g_G    [NROW*DI];
__device__ __align__(16) float g_part [(size_t)3*NROW*DI];
__device__ __align__(16) float g_opart[(size_t)6*NROW*DM];
__device__ __align__(16) unsigned g_wmask[NROW*16];
__device__ __align__(16) uint2 g_cm[BATCH*NCHUNK*TT];
__device__ int   g_nnz[NROW];
__device__ float g_invdeg[NROW];

__device__ __forceinline__ float siluf(float v){ return v / (1.f + __expf(-v)); }

// ---------------- layernorm ----------------
__global__ void ln_kernel(const float* __restrict__ x,
                          const float* __restrict__ sc,
                          const float* __restrict__ bi,
                          float* __restrict__ out)
{
    int m = blockIdx.x;
    const float* xr = x + (size_t)m*DM;
    int tid = threadIdx.x;
    float v[3]; float s=0.f, sq=0.f;
#pragma unroll
    for (int q=0;q<3;q++){ v[q]=xr[tid+q*256]; s+=v[q]; sq+=v[q]*v[q]; }
#pragma unroll
    for (int o=16;o;o>>=1){ s+=__shfl_down_sync(~0u,s,o); sq+=__shfl_down_sync(~0u,sq,o); }
    __shared__ float sh0[8], sh1[8];
    int lane=tid&31, w=tid>>5;
    if (lane==0){ sh0[w]=s; sh1[w]=sq; }
    __syncthreads();
    __shared__ float smu, srs;
    if (tid==0){
        float S=0.f,SQ=0.f;
#pragma unroll
        for (int i=0;i<8;i++){ S+=sh0[i]; SQ+=sh1[i]; }
        float mu=S/(float)DM;
        float var=SQ/(float)DM - mu*mu;
        smu=mu; srs=rsqrtf(var+1e-5f);
    }
    __syncthreads();
    float mu=smu, rs=srs;
#pragma unroll
    for (int q=0;q<3;q++){
        int k=tid+q*256;
        out[(size_t)m*DM+k] = (v[q]-mu)*rs*sc[k]+bi[k];
    }
}

// ===== 128x128x16 fp32 GEMM, 8x8 packed-f32x2 microtile, 256 threads, split-K =====
// A-fragments loaded directly as u64 pairs (consecutive m); only B packs.
template<int CONV>
__global__ __launch_bounds__(256, 2)
void gemm8(const float* __restrict__ A, int lda,
           const float* __restrict__ B, int ldb,
           float* __restrict__ Cbase, int ldc, size_t cstride,
           int Klen)
{
    __shared__ float As[2][16][132];
    __shared__ float Bs[2][16][132];
    const int tid = threadIdx.x;
    const int m0 = blockIdx.y*128, n0 = blockIdx.x*128;
    const int kbeg = blockIdx.z*Klen;
    float* C = Cbase + (size_t)blockIdx.z*cstride;
    const int tx = tid & 15, ty = tid >> 4;   // 16x16 thread grid, 8x8 microtile
    const int rb = tid >> 1;                  // loader row 0..127
    const int c8 = (tid & 1)*8;               // loader col base 0|8

    // conv incremental state (single row per thread)
    int ccur = 0, ts = 0;
    long long ao = 0;
    size_t aoff = 0;
    {
        int gm = m0 + rb;
        if (CONV){
            int cb = gm>>9, ct = gm&511;
            int tau0 = (kbeg + c8) / 1536;
            int ci0  = kbeg + c8 - tau0*1536;
            ccur = ci0;
            ts = ct + tau0 - 3;
            ao = ((long long)(cb*TT) + ts)*(2*DI) + ci0;
        } else {
            aoff = (size_t)gm*lda + kbeg + c8;
        }
    }
    const size_t boff = (size_t)(n0 + rb)*ldb + kbeg + c8;

    u64 acc2[4][8];        // [row-pair][col]; pair = rows (ty*8+2i2, ty*8+2i2+1)
#pragma unroll
    for (int i=0;i<4;i++)
#pragma unroll
        for (int j=0;j<8;j++) acc2[i][j]=0ull;

    float4 ra0, ra1, rb0, rb1;
    int koff = 0;

#define LOAD_ADV() do { \
    if (CONV){ \
        ra0 = make_float4(0.f,0.f,0.f,0.f); ra1 = ra0; \
        if (ts >= 0){ \
            ra0 = *(const float4*)(A + ao); \
            ra1 = *(const float4*)(A + ao + 4); \
        } \
    } else { \
        ra0 = *(const float4*)(A + aoff + koff); \
        ra1 = *(const float4*)(A + aoff + koff + 4); \
    } \
    rb0 = *(const float4*)(B + boff + koff); \
    rb1 = *(const float4*)(B + boff + koff + 4); \
    koff += 16; \
    if (CONV){ \
        ccur += 16; \
        long long adv = 16; \
        if (ccur >= 1536){ ccur -= 1536; adv = 16 + (2*DI - 1536); ts++; } \
        ao += adv; \
    } \
} while(0)

#define STORE_TILE(BUF_) do { \
    As[BUF_][c8+0][rb]=ra0.x; As[BUF_][c8+1][rb]=ra0.y; \
    As[BUF_][c8+2][rb]=ra0.z; As[BUF_][c8+3][rb]=ra0.w; \
    As[BUF_][c8+4][rb]=ra1.x; As[BUF_][c8+5][rb]=ra1.y; \
    As[BUF_][c8+6][rb]=ra1.z; As[BUF_][c8+7][rb]=ra1.w; \
    Bs[BUF_][c8+0][rb]=rb0.x; Bs[BUF_][c8+1][rb]=rb0.y; \
    Bs[BUF_][c8+2][rb]=rb0.z; Bs[BUF_][c8+3][rb]=rb0.w; \
    Bs[BUF_][c8+4][rb]=rb1.x; Bs[BUF_][c8+5][rb]=rb1.y; \
    Bs[BUF_][c8+6][rb]=rb1.z; Bs[BUF_][c8+7][rb]=rb1.w; \
} while(0)

    LOAD_ADV();
    STORE_TILE(0);
    __syncthreads();

    const int KT = Klen/16;
    int cur = 0;
    for (int kt=0; kt<KT; kt++){
        if (kt+1 < KT) LOAD_ADV();
#pragma unroll
        for (int k=0;k<16;k++){
            // A pairs read directly as packed u64 (consecutive m rows)
            const ulonglong2* ap = (const ulonglong2*)&As[cur][k][ty*8];
            ulonglong2 p0 = ap[0], p1 = ap[1];
            u64 av2[4] = {p0.x, p0.y, p1.x, p1.y};
            float4 b0 = *(const float4*)&Bs[cur][k][tx*8];
            float4 b1 = *(const float4*)&Bs[cur][k][tx*8+4];
            u64 bb2[8];
            bb2[0]=pack2(b0.x,b0.x); bb2[1]=pack2(b0.y,b0.y);
            bb2[2]=pack2(b0.z,b0.z); bb2[3]=pack2(b0.w,b0.w);
            bb2[4]=pack2(b1.x,b1.x); bb2[5]=pack2(b1.y,b1.y);
            bb2[6]=pack2(b1.z,b1.z); bb2[7]=pack2(b1.w,b1.w);
#pragma unroll
            for (int i=0;i<4;i++)
#pragma unroll
                for (int j=0;j<8;j++) ffma2(acc2[i][j], av2[i], bb2[j]);
        }
        if (kt+1 < KT){
            int nxt = cur^1;
            STORE_TILE(nxt);
            __syncthreads();
            cur = nxt;
        }
    }

#pragma unroll
    for (int i2=0;i2<4;i2++){
        float lo[8], hi[8];
#pragma unroll
        for (int j=0;j<8;j++) unpack2(acc2[i2][j], lo[j], hi[j]);
        int gm0 = m0 + ty*8 + 2*i2;
        float* cr0 = C + (size_t)gm0*ldc + n0 + tx*8;
        float* cr1 = C + (size_t)(gm0+1)*ldc + n0 + tx*8;
        *(float4*)(cr0)   = make_float4(lo[0],lo[1],lo[2],lo[3]);
        *(float4*)(cr0+4) = make_float4(lo[4],lo[5],lo[6],lo[7]);
        *(float4*)(cr1)   = make_float4(hi[0],hi[1],hi[2],hi[3]);
        *(float4*)(cr1+4) = make_float4(hi[4],hi[5],hi[6],hi[7]);
    }
#undef LOAD_ADV
#undef STORE_TILE
}

// ---------------- fused: conv partials + bias + silu -> xact, and x_ssm = xact @ W_x^T ----------------
__global__ void actssm_kernel(const float* __restrict__ part,
                              const float* __restrict__ cb,
                              const float* __restrict__ Wx,
                              float* __restrict__ xact,
                              float* __restrict__ xssm)
{
    int m = blockIdx.x;
    float accv[33];
#pragma unroll
    for (int n=0;n<33;n++) accv[n]=0.f;
    for (int k = threadIdx.x; k < DI; k += 256){
        size_t i = (size_t)m*DI + k;
        float v = part[i] + part[i + (size_t)NROW*DI] + part[i + 2*(size_t)NROW*DI] + cb[k];
        float xv = siluf(v);
        xact[i] = xv;
#pragma unroll
        for (int n=0;n<33;n++) accv[n] += xv * Wx[n*DI + k];
    }
    int lane=threadIdx.x&31, w=threadIdx.x>>5;
#pragma unroll
    for (int n=0;n<33;n++)
#pragma unroll
        for (int o=16;o;o>>=1) accv[n] += __shfl_down_sync(~0u, accv[n], o);
    __shared__ float sred[8][33];
    if (lane==0)
#pragma unroll
        for (int n=0;n<33;n++) sred[w][n]=accv[n];
    __syncthreads();
    if (threadIdx.x < 33){
        float s=0.f;
#pragma unroll
        for (int q=0;q<8;q++) s += sred[q][threadIdx.x];
        xssm[(size_t)m*33 + threadIdx.x] = s;
    }
}

// ---------------- combine out partials (6) + residual ----------------
__global__ void fixout_kernel(const float* __restrict__ opart,
                              const float* __restrict__ x,
                              float* __restrict__ out)
{
    int i = blockIdx.x*256 + threadIdx.x;
    if (i >= NROW*DM/4) return;
    float4 s = ((const float4*)x)[i];
#pragma unroll
    for (int p=0;p<6;p++){
        const float4 v = ((const float4*)opart)[i + (size_t)p*(NROW*DM/4)];
        s.x+=v.x; s.y+=v.y; s.z+=v.z; s.w+=v.w;
    }
    ((float4*)out)[i] = s;
}

// ---------------- conv weight re-layout (float4 writes) ----------------
__global__ void wct_kernel(const float* __restrict__ cw, float* __restrict__ wc)
{
    int idx4 = blockIdx.x*256 + threadIdx.x;
    if (idx4 >= DI*KW/4) return;
    int idx = idx4*4;
    int o = idx / KW;
    int k = idx - o*KW;
    int tau = k / DI;
    int i = k - tau*DI;
    const float* src = cw + ((size_t)o*DI + i)*KCONV + tau;
    float4 v = make_float4(src[0], src[4], src[8], src[12]);
    *(float4*)(wc + idx) = v;
}

// ---------------- adjacency bitmasks ----------------
__global__ void adj_kernel(const int* __restrict__ adj,
                           unsigned* __restrict__ wmask,
                           int* __restrict__ nnz,
                           float* __restrict__ invdeg)
{
    int rowid = blockIdx.x;
    int t = rowid & (TT-1);
    int lane = threadIdx.x;
    const int* arow = adj + (size_t)rowid*TT;
    int cnt = 0;
    for (int w = 0; w < 16; w++){
        int s = w*32 + lane;
        bool nz = (s < t) && (arow[s] != 0);
        unsigned m = __ballot_sync(~0u, nz);
        if (lane==0) wmask[rowid*16 + w] = m;
        cnt += __popc(m);
    }
    if (lane==0){
        nnz[rowid] = cnt;
        invdeg[rowid] = 1.0f / (float)(cnt < 1 ? 1 : cnt);
    }
}

// ---------------- transposed chunk masks ----------------
__global__ void cmt_kernel(const int* __restrict__ adj, uint2* __restrict__ cm)
{
    int s = threadIdx.x;
    int k = blockIdx.x;
    int b = blockIdx.y;
    int t0 = k*CH;
    unsigned m0=0, m1=0;
#pragma unroll
    for (int j=0;j<32;j++){
        int t = t0 + j;
        if (s < t && adj[((size_t)(b*TT+t))*TT + s] != 0) m0 |= 1u<<j;
    }
#pragma unroll
    for (int j=0;j<32;j++){
        int t = t0 + 32 + j;
        if (s < t && adj[((size_t)(b*TT+t))*TT + s] != 0) m1 |= 1u<<j;
    }
    cm[((size_t)b*NCHUNK + k)*TT + s] = make_uint2(m0,m1);
}

// ---------------- single-launch scan (R11 config: 128 threads, f32x2 prefill) ----------------
__global__ __launch_bounds__(SCTH, 3)
void scan_all(const float* __restrict__ xact,  const float* __restrict__ xssm,
              const float* __restrict__ xz,
              const unsigned* __restrict__ wmask, const int* __restrict__ nnz_arr,
              const float* __restrict__ invdeg,
              const float* __restrict__ Wg,    const float* __restrict__ bg,
              const float* __restrict__ Wdt,   const float* __restrict__ bdt,
              const uint2* __restrict__ cm,
              float* __restrict__ hist,        float* __restrict__ G)
{
    extern __shared__ float dsm[];
    float* lh    = dsm;                  // [CH][SCTH]
    u64*   wfp   = (u64*)(lh + LH_F);    // [16][64] packed 0/1 weights
    float* stage = lh + LH_F + WFP_F;    // [16][SCTH] hist tile
    float* sxs   = stage + STAGE_F;      // [CH][33]
    float* sxa   = sxs + SXS_F;          // [CH][8]
    float* sxz   = sxa + SXA_F;          // [CH][8]
    __shared__ unsigned char slist[CH][CH];
    __shared__ unsigned char scnt[CH];
    __shared__ float sgate[CH];
    __shared__ float sinv[CH];

    const int NB = DI/8;                 // 192
    const int b = blockIdx.x / NB;
    const int dblk = blockIdx.x - b*NB;
    const int tid = threadIdx.x;
    const int n  = tid & 15;
    const int dl = tid >> 4;             // 0..7
    const int d  = dblk*8 + dl;
    const int c  = dblk*SCTH + tid;      // this thread's hist column
    const int q  = tid & 31;             // prefill: column quad
    const int jg = tid >> 5;             // prefill: target group
    const int w = tid >> 5, lane = tid & 31;
    const int bs = tid >> 3;             // wfp build: row 0..15
    const int bj = (tid & 7) * 8;        // wfp build: target base

    float wgr[16];
#pragma unroll
    for (int m=0;m<16;m++) wgr[m] = Wg[n*16 + m];
    const float bgn  = bg[n];
    const float wdtd = Wdt[d];
    const float bdtd = bdt[d];

    const float* hbase = hist + (size_t)b*TT*ND + dblk*SCTH;

    float h = 0.f;

    for (int k = 0; k < NCHUNK; k++){
        const int t0 = k*CH;

        // ---- cross-chunk prefill: 16-row stages, packed-weight FFMA2 ----
        u64 pacc[16][2];
#pragma unroll
        for (int jj=0;jj<16;jj++){ pacc[jj][0]=0ull; pacc[jj][1]=0ull; }
        const uint2* cmb = cm + ((size_t)b*NCHUNK + k)*TT;
        for (int sb = 0; sb < t0; sb += 16){
            __syncthreads();
#pragma unroll
            for (int r = 0; r < 4; r++){
                int rr = w + r*4;
                *(float4*)&stage[rr*SCTH + lane*4] =
                    *(const float4*)(hbase + (size_t)(sb + rr)*ND + lane*4);
            }
            {
                uint2 mw = cmb[sb + bs];
#pragma unroll
                for (int e=0;e<8;e++){
                    int j = bj + e;
                    unsigned bit = (j < 32) ? ((mw.x >> j) & 1u) : ((mw.y >> (j-32)) & 1u);
                    wfp[bs*64 + j] = bit ? ONE2 : 0ull;
                }
            }
            __syncthreads();
#pragma unroll 4
            for (int ss = 0; ss < 16; ss++){
                float4 val = *(const float4*)&stage[ss*SCTH + q*4];
                u64 v01 = pack2(val.x, val.y);
                u64 v23 = pack2(val.z, val.w);
                const u64* wrow = wfp + ss*64 + jg*16;
#pragma unroll
                for (int jj = 0; jj < 16; jj++){
                    u64 w2 = wrow[jj];
                    ffma2(pacc[jj][0], v01, w2);
                    ffma2(pacc[jj][1], v23, w2);
                }
            }
        }
        __syncthreads();
#pragma unroll
        for (int jj=0;jj<16;jj++){
            float x0,y0,x1,y1;
            unpack2(pacc[jj][0], x0, y0);
            unpack2(pacc[jj][1], x1, y1);
            *(float4*)&lh[(jg*16 + jj)*SCTH + q*4] = make_float4(x0,y0,x1,y1);
        }

        // ---- stage per-chunk metadata + step inputs ----
        if (tid < CH){
            int t = t0 + tid;
            int row = b*TT + t;
            unsigned mm0 = wmask[row*16 + 2*k];
            unsigned mm1 = wmask[row*16 + 2*k+1];
            int cidx = 0;
            while (mm0){ int p=__ffs(mm0)-1; mm0 &= mm0-1; slist[tid][cidx++] = (unsigned char)p; }
            while (mm1){ int p=__ffs(mm1)-1; mm1 &= mm1-1; slist[tid][cidx++] = (unsigned char)(p+32); }
            scnt[tid] = (unsigned char)cidx;
            sgate[tid] = (nnz_arr[t] + nnz_arr[TT + t]) > 0 ? 1.f : 0.f;
            sinv[tid] = invdeg[row];
        }
        for (int i = tid; i < CH*33; i += SCTH)
            sxs[i] = xssm[((size_t)(b*TT + t0) + i/33)*33 + (i%33)];
        for (int i = tid; i < CH*8; i += SCTH){
            int rr = i>>3, dd = i&7;
            size_t row = (size_t)(b*TT + t0 + rr);
            sxa[i] = xact[row*DI + dblk*8 + dd];
            sxz[i] = xz[row*2*DI + DI + dblk*8 + dd];
        }
        __syncthreads();

        // ---- 64 sequential steps ----
        for (int tt=0; tt<CH; tt++){
            const float* xsr = &sxs[tt*33];
            float araw = xsr[0]*wdtd + bdtd;
            float dec  = 1.f/(1.f + __expf(araw));
            float xa   = sxa[tt*8 + dl];
            float Bn   = xsr[1 + n];
            float Cn   = xsr[17 + n];
            h = h*dec + Bn*xa;

            float g = lh[tt*SCTH + tid];
            int nz = scnt[tt];
            const unsigned char* lp = &slist[tt][0];
            int j = 0;
            for (; j+4 <= nz; j += 4){
                float v0 = lh[lp[j]  *SCTH + tid];
                float v1 = lh[lp[j+1]*SCTH + tid];
                float v2 = lh[lp[j+2]*SCTH + tid];
                float v3 = lh[lp[j+3]*SCTH + tid];
                g += (v0+v1) + (v2+v3);
            }
            for (; j < nz; j++) g += lh[lp[j]*SCTH + tid];
            g *= sinv[tt];

            float a = bgn;
#pragma unroll
            for (int m=0;m<16;m++)
                a += wgr[m] * __shfl_sync(0xffffffffu, g, m, 16);
            float upd = 0.1f * a / (1.f + __expf(-a));
            h += sgate[tt] * upd;

            lh[tt*SCTH + tid] = h;

            float y = h * Cn;
#pragma unroll
            for (int o=8; o; o>>=1) y += __shfl_xor_sync(0xffffffffu, y, o, 16);
            if (n == 0){
                float zz = sxz[tt*8 + dl];
                G[((size_t)(b*TT + t0 + tt))*DI + d] = y * (zz / (1.f + __expf(-zz)));
            }
        }

        // ---- flush chunk hist ----
#pragma unroll 4
        for (int tt=0; tt<CH; tt++)
            hist[((size_t)(b*TT + t0 + tt))*ND + c] = lh[tt*SCTH + tid];
    }
}

// ---------------- launch ----------------
extern "C" void kernel_launch(void* const* d_in, const int* in_sizes, int n_in,
                              void* d_out, int out_size)
{
    (void)in_sizes; (void)n_in; (void)out_size;
    const float* x        = (const float*)d_in[0];
    const int*   adj      = (const int*)  d_in[1];
    const float* ln_scale = (const float*)d_in[2];
    const float* ln_bias  = (const float*)d_in[3];
    const float* W_in     = (const float*)d_in[4];
    const float* conv_w   = (const float*)d_in[5];
    const float* conv_b   = (const float*)d_in[6];
    const float* W_x      = (const float*)d_in[7];
    const float* W_dt     = (const float*)d_in[8];
    const float* b_dt     = (const float*)d_in[9];
    const float* W_g      = (const float*)d_in[10];
    const float* b_g      = (const float*)d_in[11];
    const float* W_out    = (const float*)d_in[12];
    float* out = (float*)d_out;

    float *p_xn, *p_xz, *p_xact, *p_wc, *p_xssm, *p_hist, *p_G,
          *p_invdeg, *p_part, *p_opart;
    unsigned *p_wmask; uint2 *p_cm; int *p_nnz;
    cudaGetSymbolAddress((void**)&p_xn,    g_xn);
    cudaGetSymbolAddress((void**)&p_xz,    g_xz);
    cudaGetSymbolAddress((void**)&p_xact,  g_xact);
    cudaGetSymbolAddress((void**)&p_wc,    g_wc);
    cudaGetSymbolAddress((void**)&p_xssm,  g_xssm);
    cudaGetSymbolAddress((void**)&p_hist,  g_hist);
    cudaGetSymbolAddress((void**)&p_G,     g_G);
    cudaGetSymbolAddress((void**)&p_part,  g_part);
    cudaGetSymbolAddress((void**)&p_opart, g_opart);
    cudaGetSymbolAddress((void**)&p_wmask, g_wmask);
    cudaGetSymbolAddress((void**)&p_cm,    g_cm);
    cudaGetSymbolAddress((void**)&p_nnz,   g_nnz);
    cudaGetSymbolAddress((void**)&p_invdeg,g_invdeg);

    cudaFuncSetAttribute(scan_all, cudaFuncAttributeMaxDynamicSharedMemorySize, SCAN_DYN);

    // ---- position 4 = conv GEMM (profiled) ----
    // 1. layernorm
    ln_kernel<<<NROW, 256>>>(x, ln_scale, ln_bias, p_xn);
    // 2. xz = xn @ W_in^T
    gemm8<0><<<dim3(2*DI/128, NROW/128, 1), 256>>>(p_xn, DM, W_in, DM, p_xz, 2*DI, 0, DM);
    // 3. conv weight re-layout
    wct_kernel<<<(DI*KW/4 + 255)/256, 256>>>(conv_w, p_wc);
    // 4. conv as GEMM with fused pad (split 3)   <-- profiled
    gemm8<1><<<dim3(DI/128, NROW/128, 3), 256>>>(p_xz, 0, p_wc, KW, p_part, DI,
                                                 (size_t)NROW*DI, KW/3);
    // 5. fused combine+silu+xssm
    actssm_kernel<<<NROW, 256>>>(p_part, conv_b, W_x, p_xact, p_xssm);
    // 6. adjacency bitmasks
    adj_kernel<<<NROW, 32>>>(adj, p_wmask, p_nnz, p_invdeg);
    // 7. transposed chunk masks
    cmt_kernel<<<dim3(NCHUNK, BATCH), TT>>>(adj, p_cm);
    // 8. single-launch scan (R11 config)
    scan_all<<<BATCH*(DI/8), SCTH, SCAN_DYN>>>(
        p_xact, p_xssm, p_xz, p_wmask, p_nnz, p_invdeg,
        W_g, b_g, W_dt, b_dt, p_cm, p_hist, p_G);
    // 9. out = G @ W_out^T (split 6)
    gemm8<0><<<dim3(DM/128, NROW/128, 6), 256>>>(p_G, DI, W_out, DI, p_opart, DM,
                                                 (size_t)NROW*DM, DI/6);
    // 10. combine out partials + residual
    fixout_kernel<<<(NROW*DM/4 + 255)/256, 256>>>(p_opart, x, out);
}

// round 14
// speedup vs baseline: 1.0952x; 1.0952x over previous
#include <cuda_runtime.h>
#include <cstdint>

#define BATCH 2
#define TT 512
#define DM 768
#define DI 1536
#define DS 16
#define NROW (BATCH*TT)          // 1024
#define KCONV 4
#define KW (KCONV*DI)            // 6144
#define ND (DS*DI)               // 24576
#define CH 64
#define NCHUNK (TT/CH)           // 8
#define SCTH 128                 // scan threads: 8 dl x 16 n; 128 hist columns/block

typedef unsigned long long u64;
static __device__ __forceinline__ void ffma2(u64& d, u64 a, u64 b){
    asm("fma.rn.f32x2 %0, %1, %2, %0;" : "+l"(d) : "l"(a), "l"(b));
}
static __device__ __forceinline__ u64 pack2(float x, float y){
    u64 r; asm("mov.b64 %0, {%1, %2};" : "=l"(r) : "f"(x), "f"(y)); return r;
}
static __device__ __forceinline__ void unpack2(u64 v, float& x, float& y){
    asm("mov.b64 {%0, %1}, %2;" : "=f"(x), "=f"(y) : "l"(v));
}
#define ONE2 0x3f8000003f800000ull

// scan dynamic smem (floats)
#define LH_F    (CH*SCTH)        // 8192
#define WFP_F   (2048)           // u64 wfp[16][64] = 2048 float-equivalents
#define STAGE_F (16*SCTH)        // 2048
#define SXS_F   (CH*33)          // 2112
#define SXA_F   (CH*8)           // 512
#define SXZ_F   (CH*8)           // 512
#define SCAN_DYN ((LH_F+WFP_F+STAGE_F+SXS_F+SXA_F+SXZ_F)*sizeof(float))

// ---------------- scratch ----------------
__device__ __align__(16) float g_xn   [NROW*DM];
__device__ __align__(16) float g_xz   [NROW*2*DI];
__device__ __align__(16) float g_xact [NROW*DI];
__device__ __align__(16) float g_wc   [DI*KW];
__device__ __align__(16) float g_xssm [NROW*33];
__device__ __align__(16) float g_hist [(size_t)BATCH*TT*ND];   // block-local cols
__device__ __align__(16) float g_G    [NROW*DI];
__device__ __align__(16) float g_part [(size_t)3*NROW*DI];
__device__ __align__(16) float g_opart[(size_t)6*NROW*DM];
__device__ __align__(16) unsigned g_wmask[NROW*16];
__device__ __align__(16) uint2 g_cm[BATCH*NCHUNK*TT];
__device__ int   g_nnz[NROW];
__device__ float g_invdeg[NROW];

__device__ __forceinline__ float siluf(float v){ return v / (1.f + __expf(-v)); }

// ---------------- layernorm ----------------
__global__ void ln_kernel(const float* __restrict__ x,
                          const float* __restrict__ sc,
                          const float* __restrict__ bi,
                          float* __restrict__ out)
{
    int m = blockIdx.x;
    const float* xr = x + (size_t)m*DM;
    int tid = threadIdx.x;
    float v[3]; float s=0.f, sq=0.f;
#pragma unroll
    for (int q=0;q<3;q++){ v[q]=xr[tid+q*256]; s+=v[q]; sq+=v[q]*v[q]; }
#pragma unroll
    for (int o=16;o;o>>=1){ s+=__shfl_down_sync(~0u,s,o); sq+=__shfl_down_sync(~0u,sq,o); }
    __shared__ float sh0[8], sh1[8];
    int lane=tid&31, w=tid>>5;
    if (lane==0){ sh0[w]=s; sh1[w]=sq; }
    __syncthreads();
    __shared__ float smu, srs;
    if (tid==0){
        float S=0.f,SQ=0.f;
#pragma unroll
        for (int i=0;i<8;i++){ S+=sh0[i]; SQ+=sh1[i]; }
        float mu=S/(float)DM;
        float var=SQ/(float)DM - mu*mu;
        smu=mu; srs=rsqrtf(var+1e-5f);
    }
    __syncthreads();
    float mu=smu, rs=srs;
#pragma unroll
    for (int q=0;q<3;q++){
        int k=tid+q*256;
        out[(size_t)m*DM+k] = (v[q]-mu)*rs*sc[k]+bi[k];
    }
}

// ===== 128x128x16 fp32 GEMM, 16x8 microtile via packed f32x2, 128 threads, split-K =====
// A-fragments read directly as packed u64 pairs from SMEM (no MOV packs); only B packs.
template<int CONV>
__global__ __launch_bounds__(128, 2)
void gemm16(const float* __restrict__ A, int lda,
            const float* __restrict__ B, int ldb,
            float* __restrict__ Cbase, int ldc, size_t cstride,
            int Klen)
{
    __shared__ float As[2][16][132];
    __shared__ float Bs[2][16][132];
    const int tid = threadIdx.x;
    const int m0 = blockIdx.y*128, n0 = blockIdx.x*128;
    const int kbeg = blockIdx.z*Klen;
    float* C = Cbase + (size_t)blockIdx.z*cstride;
    const int tx = tid & 15, ty = tid >> 4;
    const int rb = tid >> 2;
    const int c4 = (tid & 3)*4;

    int ccur = 0;
    int ts[4];
    long long ao[4];
    size_t aoff[4], boff[4];
#pragma unroll
    for (int q=0;q<4;q++){
        int rA = rb + q*32;
        int gm = m0 + rA;
        if (CONV){
            int cb = gm>>9, ct = gm&511;
            int tau0 = (kbeg + c4) / 1536;
            int ci0  = kbeg + c4 - tau0*1536;
            ccur = ci0;
            ts[q] = ct + tau0 - 3;
            ao[q] = ((long long)(cb*TT) + ts[q])*(2*DI) + ci0;
            aoff[q] = 0;
        } else {
            aoff[q] = (size_t)gm*lda + kbeg + c4;
            ts[q]=0; ao[q]=0;
        }
        boff[q] = (size_t)(n0 + rA)*ldb + kbeg + c4;
    }

    u64 acc2[8][8];
#pragma unroll
    for (int i=0;i<8;i++)
#pragma unroll
        for (int j=0;j<8;j++) acc2[i][j]=0ull;

    float4 ra[4], rbv[4];
    int koff = 0;

#define LOAD_ADV() do { \
    _Pragma("unroll") \
    for (int q=0;q<4;q++){ \
        if (CONV){ \
            ra[q] = make_float4(0.f,0.f,0.f,0.f); \
            if (ts[q] >= 0) ra[q] = *(const float4*)(A + ao[q]); \
        } else { \
            ra[q] = *(const float4*)(A + aoff[q] + koff); \
        } \
        rbv[q] = *(const float4*)(B + boff[q] + koff); \
    } \
    koff += 16; \
    if (CONV){ \
        ccur += 16; \
        long long adv = 16; \
        if (ccur >= 1536){ ccur -= 1536; adv = 16 + (2*DI - 1536); \
            _Pragma("unroll") for (int q=0;q<4;q++) ts[q]++; } \
        _Pragma("unroll") for (int q=0;q<4;q++) ao[q] += adv; \
    } \
} while(0)

#define STORE_TILE(BUF_) do { \
    _Pragma("unroll") \
    for (int q=0;q<4;q++){ \
        int r = rb + q*32; \
        As[BUF_][c4+0][r]=ra[q].x; As[BUF_][c4+1][r]=ra[q].y; \
        As[BUF_][c4+2][r]=ra[q].z; As[BUF_][c4+3][r]=ra[q].w; \
        Bs[BUF_][c4+0][r]=rbv[q].x; Bs[BUF_][c4+1][r]=rbv[q].y; \
        Bs[BUF_][c4+2][r]=rbv[q].z; Bs[BUF_][c4+3][r]=rbv[q].w; \
    } \
} while(0)

    LOAD_ADV();
    STORE_TILE(0);
    __syncthreads();

    const int KT = Klen/16;
    int cur = 0;
    for (int kt=0; kt<KT; kt++){
        if (kt+1 < KT) LOAD_ADV();
#pragma unroll
        for (int k=0;k<16;k++){
            // A: 16 consecutive m floats = 8 packed u64, read directly (16B aligned)
            const ulonglong2* ap = (const ulonglong2*)&As[cur][k][ty*16];
            ulonglong2 p0 = ap[0], p1 = ap[1], p2 = ap[2], p3 = ap[3];
            u64 av2[8] = {p0.x, p0.y, p1.x, p1.y, p2.x, p2.y, p3.x, p3.y};
            float4 b0 = *(const float4*)&Bs[cur][k][tx*8];
            float4 b1 = *(const float4*)&Bs[cur][k][tx*8+4];
            u64 bb2[8];
            bb2[0]=pack2(b0.x,b0.x); bb2[1]=pack2(b0.y,b0.y);
            bb2[2]=pack2(b0.z,b0.z); bb2[3]=pack2(b0.w,b0.w);
            bb2[4]=pack2(b1.x,b1.x); bb2[5]=pack2(b1.y,b1.y);
            bb2[6]=pack2(b1.z,b1.z); bb2[7]=pack2(b1.w,b1.w);
#pragma unroll
            for (int i=0;i<8;i++)
#pragma unroll
                for (int j=0;j<8;j++) ffma2(acc2[i][j], av2[i], bb2[j]);
        }
        if (kt+1 < KT){
            int nxt = cur^1;
            STORE_TILE(nxt);
            __syncthreads();
            cur = nxt;
        }
    }

#pragma unroll
    for (int i2=0;i2<8;i2++){
        float lo[8], hi[8];
#pragma unroll
        for (int j=0;j<8;j++) unpack2(acc2[i2][j], lo[j], hi[j]);
        int gm0 = m0 + ty*16 + 2*i2;
        float* cr0 = C + (size_t)gm0*ldc + n0 + tx*8;
        float* cr1 = C + (size_t)(gm0+1)*ldc + n0 + tx*8;
        *(float4*)(cr0)   = make_float4(lo[0],lo[1],lo[2],lo[3]);
        *(float4*)(cr0+4) = make_float4(lo[4],lo[5],lo[6],lo[7]);
        *(float4*)(cr1)   = make_float4(hi[0],hi[1],hi[2],hi[3]);
        *(float4*)(cr1+4) = make_float4(hi[4],hi[5],hi[6],hi[7]);
    }
#undef LOAD_ADV
#undef STORE_TILE
}

// ---------------- fused: conv partials + bias + silu -> xact, and x_ssm = xact @ W_x^T ----------------
__global__ void actssm_kernel(const float* __restrict__ part,
                              const float* __restrict__ cb,
                              const float* __restrict__ Wx,
                              float* __restrict__ xact,
                              float* __restrict__ xssm)
{
    int m = blockIdx.x;
    float accv[33];
#pragma unroll
    for (int n=0;n<33;n++) accv[n]=0.f;
    for (int k = threadIdx.x; k < DI; k += 256){
        size_t i = (size_t)m*DI + k;
        float v = part[i] + part[i + (size_t)NROW*DI] + part[i + 2*(size_t)NROW*DI] + cb[k];
        float xv = siluf(v);
        xact[i] = xv;
#pragma unroll
        for (int n=0;n<33;n++) accv[n] += xv * Wx[n*DI + k];
    }
    int lane=threadIdx.x&31, w=threadIdx.x>>5;
#pragma unroll
    for (int n=0;n<33;n++)
#pragma unroll
        for (int o=16;o;o>>=1) accv[n] += __shfl_down_sync(~0u, accv[n], o);
    __shared__ float sred[8][33];
    if (lane==0)
#pragma unroll
        for (int n=0;n<33;n++) sred[w][n]=accv[n];
    __syncthreads();
    if (threadIdx.x < 33){
        float s=0.f;
#pragma unroll
        for (int q=0;q<8;q++) s += sred[q][threadIdx.x];
        xssm[(size_t)m*33 + threadIdx.x] = s;
    }
}

// ---------------- combine out partials (6) + residual ----------------
__global__ void fixout_kernel(const float* __restrict__ opart,
                              const float* __restrict__ x,
                              float* __restrict__ out)
{
    int i = blockIdx.x*256 + threadIdx.x;
    if (i >= NROW*DM/4) return;
    float4 s = ((const float4*)x)[i];
#pragma unroll
    for (int p=0;p<6;p++){
        const float4 v = ((const float4*)opart)[i + (size_t)p*(NROW*DM/4)];
        s.x+=v.x; s.y+=v.y; s.z+=v.z; s.w+=v.w;
    }
    ((float4*)out)[i] = s;
}

// ---------------- conv weight re-layout, fully coalesced ----------------
// block = one output channel o. Thread reads conv_w[o][i][0..3] as float4 (coalesced),
// writes wc[o][tau*DI+i] for tau=0..3 (4 coalesced stores).
__global__ __launch_bounds__(256)
void wct_kernel(const float* __restrict__ cw, float* __restrict__ wc)
{
    int o = blockIdx.x;
    const float4* src = (const float4*)(cw + (size_t)o*DI*KCONV);
    float* dst = wc + (size_t)o*KW;
#pragma unroll
    for (int r = 0; r < DI/256; r++){
        int i = threadIdx.x + r*256;
        float4 v = src[i];
        dst[0*DI + i] = v.x;
        dst[1*DI + i] = v.y;
        dst[2*DI + i] = v.z;
        dst[3*DI + i] = v.w;
    }
}

// ---------------- adjacency bitmasks ----------------
__global__ void adj_kernel(const int* __restrict__ adj,
                           unsigned* __restrict__ wmask,
                           int* __restrict__ nnz,
                           float* __restrict__ invdeg)
{
    int rowid = blockIdx.x;
    int t = rowid & (TT-1);
    int lane = threadIdx.x;
    const int* arow = adj + (size_t)rowid*TT;
    int cnt = 0;
    for (int w = 0; w < 16; w++){
        int s = w*32 + lane;
        bool nz = (s < t) && (arow[s] != 0);
        unsigned m = __ballot_sync(~0u, nz);
        if (lane==0) wmask[rowid*16 + w] = m;
        cnt += __popc(m);
    }
    if (lane==0){
        nnz[rowid] = cnt;
        invdeg[rowid] = 1.0f / (float)(cnt < 1 ? 1 : cnt);
    }
}

// ---------------- transposed chunk masks ----------------
__global__ void cmt_kernel(const int* __restrict__ adj, uint2* __restrict__ cm)
{
    int s = threadIdx.x;
    int k = blockIdx.x;
    int b = blockIdx.y;
    int t0 = k*CH;
    unsigned m0=0, m1=0;
#pragma unroll
    for (int j=0;j<32;j++){
        int t = t0 + j;
        if (s < t && adj[((size_t)(b*TT+t))*TT + s] != 0) m0 |= 1u<<j;
    }
#pragma unroll
    for (int j=0;j<32;j++){
        int t = t0 + 32 + j;
        if (s < t && adj[((size_t)(b*TT+t))*TT + s] != 0) m1 |= 1u<<j;
    }
    cm[((size_t)b*NCHUNK + k)*TT + s] = make_uint2(m0,m1);
}

// ---------------- single-launch scan (R11 config: 128 threads, f32x2 prefill) ----------------
__global__ __launch_bounds__(SCTH, 3)
void scan_all(const float* __restrict__ xact,  const float* __restrict__ xssm,
              const float* __restrict__ xz,
              const unsigned* __restrict__ wmask, const int* __restrict__ nnz_arr,
              const float* __restrict__ invdeg,
              const float* __restrict__ Wg,    const float* __restrict__ bg,
              const float* __restrict__ Wdt,   const float* __restrict__ bdt,
              const uint2* __restrict__ cm,
              float* __restrict__ hist,        float* __restrict__ G)
{
    extern __shared__ float dsm[];
    float* lh    = dsm;                  // [CH][SCTH]
    u64*   wfp   = (u64*)(lh + LH_F);    // [16][64] packed 0/1 weights
    float* stage = lh + LH_F + WFP_F;    // [16][SCTH] hist tile
    float* sxs   = stage + STAGE_F;      // [CH][33]
    float* sxa   = sxs + SXS_F;          // [CH][8]
    float* sxz   = sxa + SXA_F;          // [CH][8]
    __shared__ unsigned char slist[CH][CH];
    __shared__ unsigned char scnt[CH];
    __shared__ float sgate[CH];
    __shared__ float sinv[CH];

    const int NB = DI/8;                 // 192
    const int b = blockIdx.x / NB;
    const int dblk = blockIdx.x - b*NB;
    const int tid = threadIdx.x;
    const int n  = tid & 15;
    const int dl = tid >> 4;             // 0..7
    const int d  = dblk*8 + dl;
    const int c  = dblk*SCTH + tid;      // this thread's hist column
    const int q  = tid & 31;             // prefill: column quad
    const int jg = tid >> 5;             // prefill: target group
    const int w = tid >> 5, lane = tid & 31;
    const int bs = tid >> 3;             // wfp build: row 0..15
    const int bj = (tid & 7) * 8;        // wfp build: target base

    float wgr[16];
#pragma unroll
    for (int m=0;m<16;m++) wgr[m] = Wg[n*16 + m];
    const float bgn  = bg[n];
    const float wdtd = Wdt[d];
    const float bdtd = bdt[d];

    const float* hbase = hist + (size_t)b*TT*ND + dblk*SCTH;

    float h = 0.f;

    for (int k = 0; k < NCHUNK; k++){
        const int t0 = k*CH;

        // ---- cross-chunk prefill: 16-row stages, packed-weight FFMA2 ----
        u64 pacc[16][2];
#pragma unroll
        for (int jj=0;jj<16;jj++){ pacc[jj][0]=0ull; pacc[jj][1]=0ull; }
        const uint2* cmb = cm + ((size_t)b*NCHUNK + k)*TT;
        for (int sb = 0; sb < t0; sb += 16){
            __syncthreads();
#pragma unroll
            for (int r = 0; r < 4; r++){
                int rr = w + r*4;
                *(float4*)&stage[rr*SCTH + lane*4] =
                    *(const float4*)(hbase + (size_t)(sb + rr)*ND + lane*4);
            }
            {
                uint2 mw = cmb[sb + bs];
#pragma unroll
                for (int e=0;e<8;e++){
                    int j = bj + e;
                    unsigned bit = (j < 32) ? ((mw.x >> j) & 1u) : ((mw.y >> (j-32)) & 1u);
                    wfp[bs*64 + j] = bit ? ONE2 : 0ull;
                }
            }
            __syncthreads();
#pragma unroll 4
            for (int ss = 0; ss < 16; ss++){
                float4 val = *(const float4*)&stage[ss*SCTH + q*4];
                u64 v01 = pack2(val.x, val.y);
                u64 v23 = pack2(val.z, val.w);
                const u64* wrow = wfp + ss*64 + jg*16;
#pragma unroll
                for (int jj = 0; jj < 16; jj++){
                    u64 w2 = wrow[jj];
                    ffma2(pacc[jj][0], v01, w2);
                    ffma2(pacc[jj][1], v23, w2);
                }
            }
        }
        __syncthreads();
#pragma unroll
        for (int jj=0;jj<16;jj++){
            float x0,y0,x1,y1;
            unpack2(pacc[jj][0], x0, y0);
            unpack2(pacc[jj][1], x1, y1);
            *(float4*)&lh[(jg*16 + jj)*SCTH + q*4] = make_float4(x0,y0,x1,y1);
        }

        // ---- stage per-chunk metadata + step inputs ----
        if (tid < CH){
            int t = t0 + tid;
            int row = b*TT + t;
            unsigned mm0 = wmask[row*16 + 2*k];
            unsigned mm1 = wmask[row*16 + 2*k+1];
            int cidx = 0;
            while (mm0){ int p=__ffs(mm0)-1; mm0 &= mm0-1; slist[tid][cidx++] = (unsigned char)p; }
            while (mm1){ int p=__ffs(mm1)-1; mm1 &= mm1-1; slist[tid][cidx++] = (unsigned char)(p+32); }
            scnt[tid] = (unsigned char)cidx;
            sgate[tid] = (nnz_arr[t] + nnz_arr[TT + t]) > 0 ? 1.f : 0.f;
            sinv[tid] = invdeg[row];
        }
        for (int i = tid; i < CH*33; i += SCTH)
            sxs[i] = xssm[((size_t)(b*TT + t0) + i/33)*33 + (i%33)];
        for (int i = tid; i < CH*8; i += SCTH){
            int rr = i>>3, dd = i&7;
            size_t row = (size_t)(b*TT + t0 + rr);
            sxa[i] = xact[row*DI + dblk*8 + dd];
            sxz[i] = xz[row*2*DI + DI + dblk*8 + dd];
        }
        __syncthreads();

        // ---- 64 sequential steps ----
        for (int tt=0; tt<CH; tt++){
            const float* xsr = &sxs[tt*33];
            float araw = xsr[0]*wdtd + bdtd;
            float dec  = 1.f/(1.f + __expf(araw));
            float xa   = sxa[tt*8 + dl];
            float Bn   = xsr[1 + n];
            float Cn   = xsr[17 + n];
            h = h*dec + Bn*xa;

            float g = lh[tt*SCTH + tid];
            int nz = scnt[tt];
            const unsigned char* lp = &slist[tt][0];
            int j = 0;
            for (; j+4 <= nz; j += 4){
                float v0 = lh[lp[j]  *SCTH + tid];
                float v1 = lh[lp[j+1]*SCTH + tid];
                float v2 = lh[lp[j+2]*SCTH + tid];
                float v3 = lh[lp[j+3]*SCTH + tid];
                g += (v0+v1) + (v2+v3);
            }
            for (; j < nz; j++) g += lh[lp[j]*SCTH + tid];
            g *= sinv[tt];

            float a = bgn;
#pragma unroll
            for (int m=0;m<16;m++)
                a += wgr[m] * __shfl_sync(0xffffffffu, g, m, 16);
            float upd = 0.1f * a / (1.f + __expf(-a));
            h += sgate[tt] * upd;

            lh[tt*SCTH + tid] = h;

            float y = h * Cn;
#pragma unroll
            for (int o=8; o; o>>=1) y += __shfl_xor_sync(0xffffffffu, y, o, 16);
            if (n == 0){
                float zz = sxz[tt*8 + dl];
                G[((size_t)(b*TT + t0 + tt))*DI + d] = y * (zz / (1.f + __expf(-zz)));
            }
        }

        // ---- flush chunk hist ----
#pragma unroll 4
        for (int tt=0; tt<CH; tt++)
            hist[((size_t)(b*TT + t0 + tt))*ND + c] = lh[tt*SCTH + tid];
    }
}

// ---------------- launch ----------------
extern "C" void kernel_launch(void* const* d_in, const int* in_sizes, int n_in,
                              void* d_out, int out_size)
{
    (void)in_sizes; (void)n_in; (void)out_size;
    const float* x        = (const float*)d_in[0];
    const int*   adj      = (const int*)  d_in[1];
    const float* ln_scale = (const float*)d_in[2];
    const float* ln_bias  = (const float*)d_in[3];
    const float* W_in     = (const float*)d_in[4];
    const float* conv_w   = (const float*)d_in[5];
    const float* conv_b   = (const float*)d_in[6];
    const float* W_x      = (const float*)d_in[7];
    const float* W_dt     = (const float*)d_in[8];
    const float* b_dt     = (const float*)d_in[9];
    const float* W_g      = (const float*)d_in[10];
    const float* b_g      = (const float*)d_in[11];
    const float* W_out    = (const float*)d_in[12];
    float* out = (float*)d_out;

    float *p_xn, *p_xz, *p_xact, *p_wc, *p_xssm, *p_hist, *p_G,
          *p_invdeg, *p_part, *p_opart;
    unsigned *p_wmask; uint2 *p_cm; int *p_nnz;
    cudaGetSymbolAddress((void**)&p_xn,    g_xn);
    cudaGetSymbolAddress((void**)&p_xz,    g_xz);
    cudaGetSymbolAddress((void**)&p_xact,  g_xact);
    cudaGetSymbolAddress((void**)&p_wc,    g_wc);
    cudaGetSymbolAddress((void**)&p_xssm,  g_xssm);
    cudaGetSymbolAddress((void**)&p_hist,  g_hist);
    cudaGetSymbolAddress((void**)&p_G,     g_G);
    cudaGetSymbolAddress((void**)&p_part,  g_part);
    cudaGetSymbolAddress((void**)&p_opart, g_opart);
    cudaGetSymbolAddress((void**)&p_wmask, g_wmask);
    cudaGetSymbolAddress((void**)&p_cm,    g_cm);
    cudaGetSymbolAddress((void**)&p_nnz,   g_nnz);
    cudaGetSymbolAddress((void**)&p_invdeg,g_invdeg);

    cudaFuncSetAttribute(scan_all, cudaFuncAttributeMaxDynamicSharedMemorySize, SCAN_DYN);

    // ---- position 4 = conv GEMM (profiled) ----
    // 1. layernorm
    ln_kernel<<<NROW, 256>>>(x, ln_scale, ln_bias, p_xn);
    // 2. xz = xn @ W_in^T
    gemm16<0><<<dim3(2*DI/128, NROW/128, 1), 128>>>(p_xn, DM, W_in, DM, p_xz, 2*DI, 0, DM);
    // 3. conv weight re-layout (coalesced)
    wct_kernel<<<DI, 256>>>(conv_w, p_wc);
    // 4. conv as GEMM with fused pad (split 3)   <-- profiled
    gemm16<1><<<dim3(DI/128, NROW/128, 3), 128>>>(p_xz, 0, p_wc, KW, p_part, DI,
                                                  (size_t)NROW*DI, KW/3);
    // 5. fused combine+silu+xssm
    actssm_kernel<<<NROW, 256>>>(p_part, conv_b, W_x, p_xact, p_xssm);
    // 6. adjacency bitmasks
    adj_kernel<<<NROW, 32>>>(adj, p_wmask, p_nnz, p_invdeg);
    // 7. transposed chunk masks
    cmt_kernel<<<dim3(NCHUNK, BATCH), TT>>>(adj, p_cm);
    // 8. single-launch scan (R11 config)
    scan_all<<<BATCH*(DI/8), SCTH, SCAN_DYN>>>(
        p_xact, p_xssm, p_xz, p_wmask, p_nnz, p_invdeg,
        W_g, b_g, W_dt, b_dt, p_cm, p_hist, p_G);
    // 9. out = G @ W_out^T (split 6)
    gemm16<0><<<dim3(DM/128, NROW/128, 6), 128>>>(p_G, DI, W_out, DI, p_opart, DM,
                                                  (size_t)NROW*DM, DI/6);
    // 10. combine out partials + residual
    fixout_kernel<<<(NROW*DM/4 + 255)/256, 256>>>(p_opart, x, out);
}

// round 15
// speedup vs baseline: 1.2714x; 1.1609x over previous
#include <cuda_runtime.h>
#include <cstdint>

#define BATCH 2
#define TT 512
#define DM 768
#define DI 1536
#define DS 16
#define NROW (BATCH*TT)          // 1024
#define KCONV 4
#define KW (KCONV*DI)            // 6144
#define ND (DS*DI)               // 24576
#define CH 64
#define NCHUNK (TT/CH)           // 8
#define SCTH 128                 // scan threads: 8 dl x 16 n; 128 hist columns/block

typedef unsigned long long u64;
static __device__ __forceinline__ void ffma2(u64& d, u64 a, u64 b){
    asm("fma.rn.f32x2 %0, %1, %2, %0;" : "+l"(d) : "l"(a), "l"(b));
}
static __device__ __forceinline__ u64 pack2(float x, float y){
    u64 r; asm("mov.b64 %0, {%1, %2};" : "=l"(r) : "f"(x), "f"(y)); return r;
}
static __device__ __forceinline__ void unpack2(u64 v, float& x, float& y){
    asm("mov.b64 {%0, %1}, %2;" : "=f"(x), "=f"(y) : "l"(v));
}
static __device__ __forceinline__ float tf32r(float v){
    uint32_t u; asm("cvt.rna.tf32.f32 %0, %1;" : "=r"(u) : "f"(v));
    return __uint_as_float(u);
}

// scan dynamic smem (floats)
#define LH_F     (CH*SCTH)       // 8192
#define STG      136             // stage row stride (conflict-free mma b-loads)
#define STAGE2_F (16*STG)        // 2176
#define SXS_F    (CH*33)         // 2112
#define SXA_F    (CH*8)          // 512
#define SXZ_F    (CH*8)          // 512
#define SCAN_DYN ((LH_F+STAGE2_F+SXS_F+SXA_F+SXZ_F)*sizeof(float))   // 54016 B

// ---------------- scratch ----------------
__device__ __align__(16) float g_xn   [NROW*DM];
__device__ __align__(16) float g_xz   [NROW*2*DI];
__device__ __align__(16) float g_xact [NROW*DI];
__device__ __align__(16) float g_wc   [DI*KW];
__device__ __align__(16) float g_xssm [NROW*33];
__device__ __align__(16) float g_hist [(size_t)BATCH*TT*ND];   // block-local cols
__device__ __align__(16) float g_G    [NROW*DI];
__device__ __align__(16) float g_part [(size_t)3*NROW*DI];
__device__ __align__(16) float g_opart[(size_t)6*NROW*DM];
__device__ __align__(16) unsigned g_wmask[NROW*16];
__device__ __align__(16) uint2 g_cm[BATCH*NCHUNK*TT];
__device__ int   g_nnz[NROW];
__device__ float g_invdeg[NROW];

__device__ __forceinline__ float siluf(float v){ return v / (1.f + __expf(-v)); }

// ---------------- layernorm ----------------
__global__ void ln_kernel(const float* __restrict__ x,
                          const float* __restrict__ sc,
                          const float* __restrict__ bi,
                          float* __restrict__ out)
{
    int m = blockIdx.x;
    const float* xr = x + (size_t)m*DM;
    int tid = threadIdx.x;
    float v[3]; float s=0.f, sq=0.f;
#pragma unroll
    for (int q=0;q<3;q++){ v[q]=xr[tid+q*256]; s+=v[q]; sq+=v[q]*v[q]; }
#pragma unroll
    for (int o=16;o;o>>=1){ s+=__shfl_down_sync(~0u,s,o); sq+=__shfl_down_sync(~0u,sq,o); }
    __shared__ float sh0[8], sh1[8];
    int lane=tid&31, w=tid>>5;
    if (lane==0){ sh0[w]=s; sh1[w]=sq; }
    __syncthreads();
    __shared__ float smu, srs;
    if (tid==0){
        float S=0.f,SQ=0.f;
#pragma unroll
        for (int i=0;i<8;i++){ S+=sh0[i]; SQ+=sh1[i]; }
        float mu=S/(float)DM;
        float var=SQ/(float)DM - mu*mu;
        smu=mu; srs=rsqrtf(var+1e-5f);
    }
    __syncthreads();
    float mu=smu, rs=srs;
#pragma unroll
    for (int q=0;q<3;q++){
        int k=tid+q*256;
        out[(size_t)m*DM+k] = (v[q]-mu)*rs*sc[k]+bi[k];
    }
}

// ===== 128x128x16 fp32 GEMM, 16x8 microtile via packed f32x2, 128 threads, split-K =====
template<int CONV>
__global__ __launch_bounds__(128, 2)
void gemm16(const float* __restrict__ A, int lda,
            const float* __restrict__ B, int ldb,
            float* __restrict__ Cbase, int ldc, size_t cstride,
            int Klen)
{
    __shared__ float As[2][16][132];
    __shared__ float Bs[2][16][132];
    const int tid = threadIdx.x;
    const int m0 = blockIdx.y*128, n0 = blockIdx.x*128;
    const int kbeg = blockIdx.z*Klen;
    float* C = Cbase + (size_t)blockIdx.z*cstride;
    const int tx = tid & 15, ty = tid >> 4;
    const int rb = tid >> 2;
    const int c4 = (tid & 3)*4;

    int ccur = 0;
    int ts[4];
    long long ao[4];
    size_t aoff[4], boff[4];
#pragma unroll
    for (int q=0;q<4;q++){
        int rA = rb + q*32;
        int gm = m0 + rA;
        if (CONV){
            int cb = gm>>9, ct = gm&511;
            int tau0 = (kbeg + c4) / 1536;
            int ci0  = kbeg + c4 - tau0*1536;
            ccur = ci0;
            ts[q] = ct + tau0 - 3;
            ao[q] = ((long long)(cb*TT) + ts[q])*(2*DI) + ci0;
            aoff[q] = 0;
        } else {
            aoff[q] = (size_t)gm*lda + kbeg + c4;
            ts[q]=0; ao[q]=0;
        }
        boff[q] = (size_t)(n0 + rA)*ldb + kbeg + c4;
    }

    u64 acc2[8][8];
#pragma unroll
    for (int i=0;i<8;i++)
#pragma unroll
        for (int j=0;j<8;j++) acc2[i][j]=0ull;

    float4 ra[4], rbv[4];
    int koff = 0;

#define LOAD_ADV() do { \
    _Pragma("unroll") \
    for (int q=0;q<4;q++){ \
        if (CONV){ \
            ra[q] = make_float4(0.f,0.f,0.f,0.f); \
            if (ts[q] >= 0) ra[q] = *(const float4*)(A + ao[q]); \
        } else { \
            ra[q] = *(const float4*)(A + aoff[q] + koff); \
        } \
        rbv[q] = *(const float4*)(B + boff[q] + koff); \
    } \
    koff += 16; \
    if (CONV){ \
        ccur += 16; \
        long long adv = 16; \
        if (ccur >= 1536){ ccur -= 1536; adv = 16 + (2*DI - 1536); \
            _Pragma("unroll") for (int q=0;q<4;q++) ts[q]++; } \
        _Pragma("unroll") for (int q=0;q<4;q++) ao[q] += adv; \
    } \
} while(0)

#define STORE_TILE(BUF_) do { \
    _Pragma("unroll") \
    for (int q=0;q<4;q++){ \
        int r = rb + q*32; \
        As[BUF_][c4+0][r]=ra[q].x; As[BUF_][c4+1][r]=ra[q].y; \
        As[BUF_][c4+2][r]=ra[q].z; As[BUF_][c4+3][r]=ra[q].w; \
        Bs[BUF_][c4+0][r]=rbv[q].x; Bs[BUF_][c4+1][r]=rbv[q].y; \
        Bs[BUF_][c4+2][r]=rbv[q].z; Bs[BUF_][c4+3][r]=rbv[q].w; \
    } \
} while(0)

    LOAD_ADV();
    STORE_TILE(0);
    __syncthreads();

    const int KT = Klen/16;
    int cur = 0;
    for (int kt=0; kt<KT; kt++){
        if (kt+1 < KT) LOAD_ADV();
#pragma unroll
        for (int k=0;k<16;k++){
            const ulonglong2* ap = (const ulonglong2*)&As[cur][k][ty*16];
            ulonglong2 p0 = ap[0], p1 = ap[1], p2 = ap[2], p3 = ap[3];
            u64 av2[8] = {p0.x, p0.y, p1.x, p1.y, p2.x, p2.y, p3.x, p3.y};
            float4 b0 = *(const float4*)&Bs[cur][k][tx*8];
            float4 b1 = *(const float4*)&Bs[cur][k][tx*8+4];
            u64 bb2[8];
            bb2[0]=pack2(b0.x,b0.x); bb2[1]=pack2(b0.y,b0.y);
            bb2[2]=pack2(b0.z,b0.z); bb2[3]=pack2(b0.w,b0.w);
            bb2[4]=pack2(b1.x,b1.x); bb2[5]=pack2(b1.y,b1.y);
            bb2[6]=pack2(b1.z,b1.z); bb2[7]=pack2(b1.w,b1.w);
#pragma unroll
            for (int i=0;i<8;i++)
#pragma unroll
                for (int j=0;j<8;j++) ffma2(acc2[i][j], av2[i], bb2[j]);
        }
        if (kt+1 < KT){
            int nxt = cur^1;
            STORE_TILE(nxt);
            __syncthreads();
            cur = nxt;
        }
    }

#pragma unroll
    for (int i2=0;i2<8;i2++){
        float lo[8], hi[8];
#pragma unroll
        for (int j=0;j<8;j++) unpack2(acc2[i2][j], lo[j], hi[j]);
        int gm0 = m0 + ty*16 + 2*i2;
        float* cr0 = C + (size_t)gm0*ldc + n0 + tx*8;
        float* cr1 = C + (size_t)(gm0+1)*ldc + n0 + tx*8;
        *(float4*)(cr0)   = make_float4(lo[0],lo[1],lo[2],lo[3]);
        *(float4*)(cr0+4) = make_float4(lo[4],lo[5],lo[6],lo[7]);
        *(float4*)(cr1)   = make_float4(hi[0],hi[1],hi[2],hi[3]);
        *(float4*)(cr1+4) = make_float4(hi[4],hi[5],hi[6],hi[7]);
    }
#undef LOAD_ADV
#undef STORE_TILE
}

// ---------------- fused: conv partials + bias + silu -> xact, and x_ssm = xact @ W_x^T ----------------
__global__ void actssm_kernel(const float* __restrict__ part,
                              const float* __restrict__ cb,
                              const float* __restrict__ Wx,
                              float* __restrict__ xact,
                              float* __restrict__ xssm)
{
    int m = blockIdx.x;
    float accv[33];
#pragma unroll
    for (int n=0;n<33;n++) accv[n]=0.f;
    for (int k = threadIdx.x; k < DI; k += 256){
        size_t i = (size_t)m*DI + k;
        float v = part[i] + part[i + (size_t)NROW*DI] + part[i + 2*(size_t)NROW*DI] + cb[k];
        float xv = siluf(v);
        xact[i] = xv;
#pragma unroll
        for (int n=0;n<33;n++) accv[n] += xv * Wx[n*DI + k];
    }
    int lane=threadIdx.x&31, w=threadIdx.x>>5;
#pragma unroll
    for (int n=0;n<33;n++)
#pragma unroll
        for (int o=16;o;o>>=1) accv[n] += __shfl_down_sync(~0u, accv[n], o);
    __shared__ float sred[8][33];
    if (lane==0)
#pragma unroll
        for (int n=0;n<33;n++) sred[w][n]=accv[n];
    __syncthreads();
    if (threadIdx.x < 33){
        float s=0.f;
#pragma unroll
        for (int q=0;q<8;q++) s += sred[q][threadIdx.x];
        xssm[(size_t)m*33 + threadIdx.x] = s;
    }
}

// ---------------- combine out partials (6) + residual ----------------
__global__ void fixout_kernel(const float* __restrict__ opart,
                              const float* __restrict__ x,
                              float* __restrict__ out)
{
    int i = blockIdx.x*256 + threadIdx.x;
    if (i >= NROW*DM/4) return;
    float4 s = ((const float4*)x)[i];
#pragma unroll
    for (int p=0;p<6;p++){
        const float4 v = ((const float4*)opart)[i + (size_t)p*(NROW*DM/4)];
        s.x+=v.x; s.y+=v.y; s.z+=v.z; s.w+=v.w;
    }
    ((float4*)out)[i] = s;
}

// ---------------- conv weight re-layout, fully coalesced ----------------
__global__ __launch_bounds__(256)
void wct_kernel(const float* __restrict__ cw, float* __restrict__ wc)
{
    int o = blockIdx.x;
    const float4* src = (const float4*)(cw + (size_t)o*DI*KCONV);
    float* dst = wc + (size_t)o*KW;
#pragma unroll
    for (int r = 0; r < DI/256; r++){
        int i = threadIdx.x + r*256;
        float4 v = src[i];
        dst[0*DI + i] = v.x;
        dst[1*DI + i] = v.y;
        dst[2*DI + i] = v.z;
        dst[3*DI + i] = v.w;
    }
}

// ---------------- adjacency bitmasks ----------------
__global__ void adj_kernel(const int* __restrict__ adj,
                           unsigned* __restrict__ wmask,
                           int* __restrict__ nnz,
                           float* __restrict__ invdeg)
{
    int rowid = blockIdx.x;
    int t = rowid & (TT-1);
    int lane = threadIdx.x;
    const int* arow = adj + (size_t)rowid*TT;
    int cnt = 0;
    for (int w = 0; w < 16; w++){
        int s = w*32 + lane;
        bool nz = (s < t) && (arow[s] != 0);
        unsigned m = __ballot_sync(~0u, nz);
        if (lane==0) wmask[rowid*16 + w] = m;
        cnt += __popc(m);
    }
    if (lane==0){
        nnz[rowid] = cnt;
        invdeg[rowid] = 1.0f / (float)(cnt < 1 ? 1 : cnt);
    }
}

// ---------------- transposed chunk masks ----------------
__global__ void cmt_kernel(const int* __restrict__ adj, uint2* __restrict__ cm)
{
    int s = threadIdx.x;
    int k = blockIdx.x;
    int b = blockIdx.y;
    int t0 = k*CH;
    unsigned m0=0, m1=0;
#pragma unroll
    for (int j=0;j<32;j++){
        int t = t0 + j;
        if (s < t && adj[((size_t)(b*TT+t))*TT + s] != 0) m0 |= 1u<<j;
    }
#pragma unroll
    for (int j=0;j<32;j++){
        int t = t0 + 32 + j;
        if (s < t && adj[((size_t)(b*TT+t))*TT + s] != 0) m1 |= 1u<<j;
    }
    cm[((size_t)b*NCHUNK + k)*TT + s] = make_uint2(m0,m1);
}

// ---------------- single-launch scan: tf32 mma.sync prefill ----------------
// Prefill: Gpast[64 targets][128 cols] = W(0/1)[64][t0] @ Hist[t0][128] on the tensor pipe.
// A-fragments synthesized from adjacency bits; B from staged hist (tf32-rounded at staging).
__global__ __launch_bounds__(SCTH, 3)
void scan_all(const float* __restrict__ xact,  const float* __restrict__ xssm,
              const float* __restrict__ xz,
              const unsigned* __restrict__ wmask, const int* __restrict__ nnz_arr,
              const float* __restrict__ invdeg,
              const float* __restrict__ Wg,    const float* __restrict__ bg,
              const float* __restrict__ Wdt,   const float* __restrict__ bdt,
              const uint2* __restrict__ cm,
              float* __restrict__ hist,        float* __restrict__ G)
{
    extern __shared__ float dsm[];
    float* lh    = dsm;                  // [CH][SCTH]
    float* stage = lh + LH_F;            // [16][STG] hist tile (tf32-rounded)
    float* sxs   = stage + STAGE2_F;     // [CH][33]
    float* sxa   = sxs + SXS_F;          // [CH][8]
    float* sxz   = sxa + SXA_F;          // [CH][8]
    __shared__ uint2 scm[16];
    __shared__ unsigned char slist[CH][CH];
    __shared__ unsigned char scnt[CH];
    __shared__ float sgate[CH];
    __shared__ float sinv[CH];

    const int NB = DI/8;                 // 192
    const int b = blockIdx.x / NB;
    const int dblk = blockIdx.x - b*NB;
    const int tid = threadIdx.x;
    const int n  = tid & 15;
    const int dl = tid >> 4;             // 0..7
    const int d  = dblk*8 + dl;
    const int c  = dblk*SCTH + tid;      // this thread's hist column
    const int wid = tid >> 5, lane = tid & 31;
    // mma fragment roles
    const int rA = lane >> 2;            // 0..7
    const int cA = lane & 3;             // 0..3
    const int j0 = (wid & 1)*16 + rA;    // bit index within 32-bit mask word
    const bool hiw = (wid >= 2);         // warps 2,3 use .y word (targets 32..63)

    float wgr[16];
#pragma unroll
    for (int m=0;m<16;m++) wgr[m] = Wg[n*16 + m];
    const float bgn  = bg[n];
    const float wdtd = Wdt[d];
    const float bdtd = bdt[d];

    const float* hbase = hist + (size_t)b*TT*ND + dblk*SCTH;

    float h = 0.f;

    for (int k = 0; k < NCHUNK; k++){
        const int t0 = k*CH;

        // ---- cross-chunk prefill via tensor-core tf32 MMA ----
        float cacc[16][4];
#pragma unroll
        for (int t_=0;t_<16;t_++)
#pragma unroll
            for (int e=0;e<4;e++) cacc[t_][e]=0.f;
        const uint2* cmb = cm + ((size_t)b*NCHUNK + k)*TT;
        for (int sb = 0; sb < t0; sb += 16){
            __syncthreads();     // also orders prior-chunk flush before stage/lh reuse
#pragma unroll
            for (int r = 0; r < 4; r++){
                int rr = wid + r*4;
                float4 v = *(const float4*)(hbase + (size_t)(sb + rr)*ND + lane*4);
                v.x = tf32r(v.x); v.y = tf32r(v.y); v.z = tf32r(v.z); v.w = tf32r(v.w);
                *(float4*)&stage[rr*STG + lane*4] = v;
            }
            if (tid < 16) scm[tid] = cmb[sb + tid];
            __syncthreads();
#pragma unroll
            for (int ks = 0; ks < 2; ks++){
                int s0 = ks*8;
                uint2 w0 = scm[s0 + cA];
                uint2 w1 = scm[s0 + cA + 4];
                unsigned m0w = hiw ? w0.y : w0.x;
                unsigned m1w = hiw ? w1.y : w1.x;
                uint32_t a0 = ((m0w >> j0) & 1u)       ? 0x3f800000u : 0u;
                uint32_t a1 = ((m0w >> (j0+8)) & 1u)   ? 0x3f800000u : 0u;
                uint32_t a2 = ((m1w >> j0) & 1u)       ? 0x3f800000u : 0u;
                uint32_t a3 = ((m1w >> (j0+8)) & 1u)   ? 0x3f800000u : 0u;
                const float* bp0 = &stage[(s0 + cA)*STG + rA];
                const float* bp1 = &stage[(s0 + cA + 4)*STG + rA];
#pragma unroll
                for (int tile = 0; tile < 16; tile++){
                    uint32_t bf0 = __float_as_uint(bp0[tile*8]);
                    uint32_t bf1 = __float_as_uint(bp1[tile*8]);
                    asm volatile("mma.sync.aligned.m16n8k8.row.col.f32.tf32.tf32.f32 "
                        "{%0,%1,%2,%3}, {%4,%5,%6,%7}, {%8,%9}, {%0,%1,%2,%3};"
                        : "+f"(cacc[tile][0]),"+f"(cacc[tile][1]),
                          "+f"(cacc[tile][2]),"+f"(cacc[tile][3])
                        : "r"(a0),"r"(a1),"r"(a2),"r"(a3),"r"(bf0),"r"(bf1));
                }
            }
        }
        // park C fragments into lh: row = wid*16 + rA (+8), col = tile*8 + 2*cA (+1)
#pragma unroll
        for (int tile = 0; tile < 16; tile++){
            int col = tile*8 + 2*cA;
            int row = wid*16 + rA;
            *(float2*)&lh[row*SCTH + col]     = make_float2(cacc[tile][0], cacc[tile][1]);
            *(float2*)&lh[(row+8)*SCTH + col] = make_float2(cacc[tile][2], cacc[tile][3]);
        }

        // ---- stage per-chunk metadata + step inputs ----
        if (tid < CH){
            int t = t0 + tid;
            int row = b*TT + t;
            unsigned mm0 = wmask[row*16 + 2*k];
            unsigned mm1 = wmask[row*16 + 2*k+1];
            int cidx = 0;
            while (mm0){ int p=__ffs(mm0)-1; mm0 &= mm0-1; slist[tid][cidx++] = (unsigned char)p; }
            while (mm1){ int p=__ffs(mm1)-1; mm1 &= mm1-1; slist[tid][cidx++] = (unsigned char)(p+32); }
            scnt[tid] = (unsigned char)cidx;
            sgate[tid] = (nnz_arr[t] + nnz_arr[TT + t]) > 0 ? 1.f : 0.f;
            sinv[tid] = invdeg[row];
        }
        for (int i = tid; i < CH*33; i += SCTH)
            sxs[i] = xssm[((size_t)(b*TT + t0) + i/33)*33 + (i%33)];
        for (int i = tid; i < CH*8; i += SCTH){
            int rr = i>>3, dd = i&7;
            size_t row = (size_t)(b*TT + t0 + rr);
            sxa[i] = xact[row*DI + dblk*8 + dd];
            sxz[i] = xz[row*2*DI + DI + dblk*8 + dd];
        }
        __syncthreads();

        // ---- 64 sequential steps ----
        for (int tt=0; tt<CH; tt++){
            const float* xsr = &sxs[tt*33];
            float araw = xsr[0]*wdtd + bdtd;
            float dec  = 1.f/(1.f + __expf(araw));
            float xa   = sxa[tt*8 + dl];
            float Bn   = xsr[1 + n];
            float Cn   = xsr[17 + n];
            h = h*dec + Bn*xa;

            float g = lh[tt*SCTH + tid];
            int nz = scnt[tt];
            const unsigned char* lp = &slist[tt][0];
            int j = 0;
            for (; j+4 <= nz; j += 4){
                float v0 = lh[lp[j]  *SCTH + tid];
                float v1 = lh[lp[j+1]*SCTH + tid];
                float v2 = lh[lp[j+2]*SCTH + tid];
                float v3 = lh[lp[j+3]*SCTH + tid];
                g += (v0+v1) + (v2+v3);
            }
            for (; j < nz; j++) g += lh[lp[j]*SCTH + tid];
            g *= sinv[tt];

            float a = bgn;
#pragma unroll
            for (int m=0;m<16;m++)
                a += wgr[m] * __shfl_sync(0xffffffffu, g, m, 16);
            float upd = 0.1f * a / (1.f + __expf(-a));
            h += sgate[tt] * upd;

            lh[tt*SCTH + tid] = h;

            float y = h * Cn;
#pragma unroll
            for (int o=8; o; o>>=1) y += __shfl_xor_sync(0xffffffffu, y, o, 16);
            if (n == 0){
                float zz = sxz[tt*8 + dl];
                G[((size_t)(b*TT + t0 + tt))*DI + d] = y * (zz / (1.f + __expf(-zz)));
            }
        }

        // ---- flush chunk hist ----
#pragma unroll 4
        for (int tt=0; tt<CH; tt++)
            hist[((size_t)(b*TT + t0 + tt))*ND + c] = lh[tt*SCTH + tid];
    }
}

// ---------------- launch ----------------
extern "C" void kernel_launch(void* const* d_in, const int* in_sizes, int n_in,
                              void* d_out, int out_size)
{
    (void)in_sizes; (void)n_in; (void)out_size;
    const float* x        = (const float*)d_in[0];
    const int*   adj      = (const int*)  d_in[1];
    const float* ln_scale = (const float*)d_in[2];
    const float* ln_bias  = (const float*)d_in[3];
    const float* W_in     = (const float*)d_in[4];
    const float* conv_w   = (const float*)d_in[5];
    const float* conv_b   = (const float*)d_in[6];
    const float* W_x      = (const float*)d_in[7];
    const float* W_dt     = (const float*)d_in[8];
    const float* b_dt     = (const float*)d_in[9];
    const float* W_g      = (const float*)d_in[10];
    const float* b_g      = (const float*)d_in[11];
    const float* W_out    = (const float*)d_in[12];
    float* out = (float*)d_out;

    float *p_xn, *p_xz, *p_xact, *p_wc, *p_xssm, *p_hist, *p_G,
          *p_invdeg, *p_part, *p_opart;
    unsigned *p_wmask; uint2 *p_cm; int *p_nnz;
    cudaGetSymbolAddress((void**)&p_xn,    g_xn);
    cudaGetSymbolAddress((void**)&p_xz,    g_xz);
    cudaGetSymbolAddress((void**)&p_xact,  g_xact);
    cudaGetSymbolAddress((void**)&p_wc,    g_wc);
    cudaGetSymbolAddress((void**)&p_xssm,  g_xssm);
    cudaGetSymbolAddress((void**)&p_hist,  g_hist);
    cudaGetSymbolAddress((void**)&p_G,     g_G);
    cudaGetSymbolAddress((void**)&p_part,  g_part);
    cudaGetSymbolAddress((void**)&p_opart, g_opart);
    cudaGetSymbolAddress((void**)&p_wmask, g_wmask);
    cudaGetSymbolAddress((void**)&p_cm,    g_cm);
    cudaGetSymbolAddress((void**)&p_nnz,   g_nnz);
    cudaGetSymbolAddress((void**)&p_invdeg,g_invdeg);

    cudaFuncSetAttribute(scan_all, cudaFuncAttributeMaxDynamicSharedMemorySize, SCAN_DYN);

    // ---- position 4 = conv GEMM (profiled) ----
    // 1. layernorm
    ln_kernel<<<NROW, 256>>>(x, ln_scale, ln_bias, p_xn);
    // 2. xz = xn @ W_in^T
    gemm16<0><<<dim3(2*DI/128, NROW/128, 1), 128>>>(p_xn, DM, W_in, DM, p_xz, 2*DI, 0, DM);
    // 3. conv weight re-layout (coalesced)
    wct_kernel<<<DI, 256>>>(conv_w, p_wc);
    // 4. conv as GEMM with fused pad (split 3)   <-- profiled
    gemm16<1><<<dim3(DI/128, NROW/128, 3), 128>>>(p_xz, 0, p_wc, KW, p_part, DI,
                                                  (size_t)NROW*DI, KW/3);
    // 5. fused combine+silu+xssm
    actssm_kernel<<<NROW, 256>>>(p_part, conv_b, W_x, p_xact, p_xssm);
    // 6. adjacency bitmasks
    adj_kernel<<<NROW, 32>>>(adj, p_wmask, p_nnz, p_invdeg);
    // 7. transposed chunk masks
    cmt_kernel<<<dim3(NCHUNK, BATCH), TT>>>(adj, p_cm);
    // 8. single-launch scan (tf32 mma prefill)
    scan_all<<<BATCH*(DI/8), SCTH, SCAN_DYN>>>(
        p_xact, p_xssm, p_xz, p_wmask, p_nnz, p_invdeg,
        W_g, b_g, W_dt, b_dt, p_cm, p_hist, p_G);
    // 9. out = G @ W_out^T (split 6)
    gemm16<0><<<dim3(DM/128, NROW/128, 6), 128>>>(p_G, DI, W_out, DI, p_opart, DM,
                                                  (size_t)NROW*DM, DI/6);
    // 10. combine out partials + residual
    fixout_kernel<<<(NROW*DM/4 + 255)/256, 256>>>(p_opart, x, out);
}

// round 16
// speedup vs baseline: 1.5192x; 1.1949x over previous
#include <cuda_runtime.h>
#include <cstdint>

#define BATCH 2
#define TT 512
#define DM 768
#define DI 1536
#define DS 16
#define NROW (BATCH*TT)          // 1024
#define KCONV 4
#define KW (KCONV*DI)            // 6144
#define ND (DS*DI)               // 24576
#define CH 64
#define NCHUNK (TT/CH)           // 8
#define SCTH 128                 // scan threads: 8 dl x 16 n; 128 hist columns/block

typedef unsigned long long u64;
static __device__ __forceinline__ float tf32r(float v){
    uint32_t u; asm("cvt.rna.tf32.f32 %0, %1;" : "=r"(u) : "f"(v));
    return __uint_as_float(u);
}
static __device__ __forceinline__ void mma_tf32(float* c, uint32_t a0, uint32_t a1,
                                                uint32_t a2, uint32_t a3,
                                                uint32_t b0, uint32_t b1){
    asm volatile("mma.sync.aligned.m16n8k8.row.col.f32.tf32.tf32.f32 "
        "{%0,%1,%2,%3}, {%4,%5,%6,%7}, {%8,%9}, {%0,%1,%2,%3};"
        : "+f"(c[0]),"+f"(c[1]),"+f"(c[2]),"+f"(c[3])
        : "r"(a0),"r"(a1),"r"(a2),"r"(a3),"r"(b0),"r"(b1));
}

// scan dynamic smem (floats)
#define LH_F     (CH*SCTH)       // 8192
#define STG      136             // stage row stride (conflict-free mma b-loads)
#define STAGE2_F (16*STG)        // 2176
#define SXS_F    (CH*33)         // 2112
#define SXA_F    (CH*8)          // 512
#define SXZ_F    (CH*8)          // 512
#define SCAN_DYN ((LH_F+STAGE2_F+SXS_F+SXA_F+SXZ_F)*sizeof(float))   // 54016 B

// ---------------- scratch ----------------
__device__ __align__(16) float g_xn   [NROW*DM];
__device__ __align__(16) float g_xz   [NROW*2*DI];
__device__ __align__(16) float g_xact [NROW*DI];
__device__ __align__(16) float g_wc   [DI*KW];
__device__ __align__(16) float g_xssm [NROW*33];
__device__ __align__(16) float g_hist [(size_t)BATCH*TT*ND];   // block-local cols
__device__ __align__(16) float g_G    [NROW*DI];
__device__ __align__(16) float g_part [(size_t)3*NROW*DI];
__device__ __align__(16) float g_opart[(size_t)6*NROW*DM];
__device__ __align__(16) unsigned g_wmask[NROW*16];
__device__ __align__(16) uint2 g_cm[BATCH*NCHUNK*TT];
__device__ int   g_nnz[NROW];
__device__ float g_invdeg[NROW];

__device__ __forceinline__ float siluf(float v){ return v / (1.f + __expf(-v)); }

// ---------------- layernorm ----------------
__global__ void ln_kernel(const float* __restrict__ x,
                          const float* __restrict__ sc,
                          const float* __restrict__ bi,
                          float* __restrict__ out)
{
    int m = blockIdx.x;
    const float* xr = x + (size_t)m*DM;
    int tid = threadIdx.x;
    float v[3]; float s=0.f, sq=0.f;
#pragma unroll
    for (int q=0;q<3;q++){ v[q]=xr[tid+q*256]; s+=v[q]; sq+=v[q]*v[q]; }
#pragma unroll
    for (int o=16;o;o>>=1){ s+=__shfl_down_sync(~0u,s,o); sq+=__shfl_down_sync(~0u,sq,o); }
    __shared__ float sh0[8], sh1[8];
    int lane=tid&31, w=tid>>5;
    if (lane==0){ sh0[w]=s; sh1[w]=sq; }
    __syncthreads();
    __shared__ float smu, srs;
    if (tid==0){
        float S=0.f,SQ=0.f;
#pragma unroll
        for (int i=0;i<8;i++){ S+=sh0[i]; SQ+=sh1[i]; }
        float mu=S/(float)DM;
        float var=SQ/(float)DM - mu*mu;
        smu=mu; srs=rsqrtf(var+1e-5f);
    }
    __syncthreads();
    float mu=smu, rs=srs;
#pragma unroll
    for (int q=0;q<3;q++){
        int k=tid+q*256;
        out[(size_t)m*DM+k] = (v[q]-mu)*rs*sc[k]+bi[k];
    }
}

// ===== 128x128x16 single-pass tf32 mma GEMM, 256 threads (8 warps, 4M x 2N), split-K =====
// A stored [k][m] in SMEM, B stored [k][n]; tf32-rounded at staging.
// Fragment/park layouts identical to the R15-validated prefill mma.
template<int CONV>
__global__ __launch_bounds__(256, 2)
void gemmtf(const float* __restrict__ A, int lda,
            const float* __restrict__ B, int ldb,
            float* __restrict__ Cbase, int ldc, size_t cstride,
            int Klen)
{
    __shared__ float As[2][16][132];
    __shared__ float Bs[2][16][132];
    const int tid = threadIdx.x;
    const int m0 = blockIdx.y*128, n0 = blockIdx.x*128;
    const int kbeg = blockIdx.z*Klen;
    float* C = Cbase + (size_t)blockIdx.z*cstride;
    const int lane = tid & 31, wid = tid >> 5;
    const int rA = lane >> 2, cA = lane & 3;
    const int wm = wid >> 1, wn = wid & 1;   // warp tile: 32M x 64N
    // loader: thread handles row rb, cols c8..c8+7
    const int rb = tid >> 1, c8 = (tid & 1)*8;

    // conv incremental window state (single row)
    int ccur = 0, ts = 0;
    long long ao = 0;
    size_t aoff = 0;
    {
        int gm = m0 + rb;
        if (CONV){
            int cb = gm>>9, ct = gm&511;
            int tau0 = (kbeg + c8) / 1536;
            int ci0  = kbeg + c8 - tau0*1536;
            ccur = ci0;
            ts = ct + tau0 - 3;
            ao = ((long long)(cb*TT) + ts)*(2*DI) + ci0;
        } else {
            aoff = (size_t)gm*lda + kbeg + c8;
        }
    }
    const size_t boff = (size_t)(n0 + rb)*ldb + kbeg + c8;

    float cacc[2][8][4];
#pragma unroll
    for (int mt=0;mt<2;mt++)
#pragma unroll
        for (int nt=0;nt<8;nt++)
#pragma unroll
            for (int e=0;e<4;e++) cacc[mt][nt][e]=0.f;

    float4 ra0, ra1, rb0, rb1;
    int koff = 0;

#define LOAD_ADV() do { \
    if (CONV){ \
        ra0 = make_float4(0.f,0.f,0.f,0.f); ra1 = ra0; \
        if (ts >= 0){ \
            ra0 = *(const float4*)(A + ao); \
            ra1 = *(const float4*)(A + ao + 4); \
        } \
    } else { \
        ra0 = *(const float4*)(A + aoff + koff); \
        ra1 = *(const float4*)(A + aoff + koff + 4); \
    } \
    rb0 = *(const float4*)(B + boff + koff); \
    rb1 = *(const float4*)(B + boff + koff + 4); \
    koff += 16; \
    if (CONV){ \
        ccur += 16; \
        long long adv = 16; \
        if (ccur >= 1536){ ccur -= 1536; adv = 16 + (2*DI - 1536); ts++; } \
        ao += adv; \
    } \
} while(0)

#define STORE_TILE(BUF_) do { \
    As[BUF_][c8+0][rb]=tf32r(ra0.x); As[BUF_][c8+1][rb]=tf32r(ra0.y); \
    As[BUF_][c8+2][rb]=tf32r(ra0.z); As[BUF_][c8+3][rb]=tf32r(ra0.w); \
    As[BUF_][c8+4][rb]=tf32r(ra1.x); As[BUF_][c8+5][rb]=tf32r(ra1.y); \
    As[BUF_][c8+6][rb]=tf32r(ra1.z); As[BUF_][c8+7][rb]=tf32r(ra1.w); \
    Bs[BUF_][c8+0][rb]=tf32r(rb0.x); Bs[BUF_][c8+1][rb]=tf32r(rb0.y); \
    Bs[BUF_][c8+2][rb]=tf32r(rb0.z); Bs[BUF_][c8+3][rb]=tf32r(rb0.w); \
    Bs[BUF_][c8+4][rb]=tf32r(rb1.x); Bs[BUF_][c8+5][rb]=tf32r(rb1.y); \
    Bs[BUF_][c8+6][rb]=tf32r(rb1.z); Bs[BUF_][c8+7][rb]=tf32r(rb1.w); \
} while(0)

    LOAD_ADV();
    STORE_TILE(0);
    __syncthreads();

    const int KT = Klen/16;
    int cur = 0;
    for (int kt=0; kt<KT; kt++){
        if (kt+1 < KT) LOAD_ADV();
#pragma unroll
        for (int ks=0; ks<16; ks+=8){
            // A fragments for both m16 tiles (row-major A: m x k)
            uint32_t afr[2][4];
#pragma unroll
            for (int mt=0;mt<2;mt++){
                int base = wm*32 + mt*16;
                afr[mt][0] = __float_as_uint(As[cur][ks+cA  ][base+rA  ]);
                afr[mt][1] = __float_as_uint(As[cur][ks+cA  ][base+rA+8]);
                afr[mt][2] = __float_as_uint(As[cur][ks+cA+4][base+rA  ]);
                afr[mt][3] = __float_as_uint(As[cur][ks+cA+4][base+rA+8]);
            }
#pragma unroll
            for (int nt=0;nt<8;nt++){
                int col = wn*64 + nt*8 + rA;
                uint32_t b0 = __float_as_uint(Bs[cur][ks+cA  ][col]);
                uint32_t b1 = __float_as_uint(Bs[cur][ks+cA+4][col]);
                mma_tf32(cacc[0][nt], afr[0][0],afr[0][1],afr[0][2],afr[0][3], b0,b1);
                mma_tf32(cacc[1][nt], afr[1][0],afr[1][1],afr[1][2],afr[1][3], b0,b1);
            }
        }
        if (kt+1 < KT){
            int nxt = cur^1;
            STORE_TILE(nxt);
            __syncthreads();
            cur = nxt;
        }
    }

    // epilogue: C fragment layout (validated in R15 park): c0,c1 -> (rA, 2cA..), c2,c3 -> (rA+8, 2cA..)
#pragma unroll
    for (int mt=0;mt<2;mt++){
        int gm = m0 + wm*32 + mt*16 + rA;
#pragma unroll
        for (int nt=0;nt<8;nt++){
            int gn = n0 + wn*64 + nt*8 + 2*cA;
            *(float2*)(C + (size_t)gm*ldc + gn)     = make_float2(cacc[mt][nt][0], cacc[mt][nt][1]);
            *(float2*)(C + (size_t)(gm+8)*ldc + gn) = make_float2(cacc[mt][nt][2], cacc[mt][nt][3]);
        }
    }
#undef LOAD_ADV
#undef STORE_TILE
}

// ---------------- fused: conv partials + bias + silu -> xact, and x_ssm = xact @ W_x^T ----------------
__global__ void actssm_kernel(const float* __restrict__ part,
                              const float* __restrict__ cb,
                              const float* __restrict__ Wx,
                              float* __restrict__ xact,
                              float* __restrict__ xssm)
{
    int m = blockIdx.x;
    float accv[33];
#pragma unroll
    for (int n=0;n<33;n++) accv[n]=0.f;
    for (int k = threadIdx.x; k < DI; k += 256){
        size_t i = (size_t)m*DI + k;
        float v = part[i] + part[i + (size_t)NROW*DI] + part[i + 2*(size_t)NROW*DI] + cb[k];
        float xv = siluf(v);
        xact[i] = xv;
#pragma unroll
        for (int n=0;n<33;n++) accv[n] += xv * Wx[n*DI + k];
    }
    int lane=threadIdx.x&31, w=threadIdx.x>>5;
#pragma unroll
    for (int n=0;n<33;n++)
#pragma unroll
        for (int o=16;o;o>>=1) accv[n] += __shfl_down_sync(~0u, accv[n], o);
    __shared__ float sred[8][33];
    if (lane==0)
#pragma unroll
        for (int n=0;n<33;n++) sred[w][n]=accv[n];
    __syncthreads();
    if (threadIdx.x < 33){
        float s=0.f;
#pragma unroll
        for (int q=0;q<8;q++) s += sred[q][threadIdx.x];
        xssm[(size_t)m*33 + threadIdx.x] = s;
    }
}

// ---------------- combine out partials (6) + residual ----------------
__global__ void fixout_kernel(const float* __restrict__ opart,
                              const float* __restrict__ x,
                              float* __restrict__ out)
{
    int i = blockIdx.x*256 + threadIdx.x;
    if (i >= NROW*DM/4) return;
    float4 s = ((const float4*)x)[i];
#pragma unroll
    for (int p=0;p<6;p++){
        const float4 v = ((const float4*)opart)[i + (size_t)p*(NROW*DM/4)];
        s.x+=v.x; s.y+=v.y; s.z+=v.z; s.w+=v.w;
    }
    ((float4*)out)[i] = s;
}

// ---------------- conv weight re-layout, fully coalesced ----------------
__global__ __launch_bounds__(256)
void wct_kernel(const float* __restrict__ cw, float* __restrict__ wc)
{
    int o = blockIdx.x;
    const float4* src = (const float4*)(cw + (size_t)o*DI*KCONV);
    float* dst = wc + (size_t)o*KW;
#pragma unroll
    for (int r = 0; r < DI/256; r++){
        int i = threadIdx.x + r*256;
        float4 v = src[i];
        dst[0*DI + i] = v.x;
        dst[1*DI + i] = v.y;
        dst[2*DI + i] = v.z;
        dst[3*DI + i] = v.w;
    }
}

// ---------------- adjacency bitmasks ----------------
__global__ void adj_kernel(const int* __restrict__ adj,
                           unsigned* __restrict__ wmask,
                           int* __restrict__ nnz,
                           float* __restrict__ invdeg)
{
    int rowid = blockIdx.x;
    int t = rowid & (TT-1);
    int lane = threadIdx.x;
    const int* arow = adj + (size_t)rowid*TT;
    int cnt = 0;
    for (int w = 0; w < 16; w++){
        int s = w*32 + lane;
        bool nz = (s < t) && (arow[s] != 0);
        unsigned m = __ballot_sync(~0u, nz);
        if (lane==0) wmask[rowid*16 + w] = m;
        cnt += __popc(m);
    }
    if (lane==0){
        nnz[rowid] = cnt;
        invdeg[rowid] = 1.0f / (float)(cnt < 1 ? 1 : cnt);
    }
}

// ---------------- transposed chunk masks ----------------
__global__ void cmt_kernel(const int* __restrict__ adj, uint2* __restrict__ cm)
{
    int s = threadIdx.x;
    int k = blockIdx.x;
    int b = blockIdx.y;
    int t0 = k*CH;
    unsigned m0=0, m1=0;
#pragma unroll
    for (int j=0;j<32;j++){
        int t = t0 + j;
        if (s < t && adj[((size_t)(b*TT+t))*TT + s] != 0) m0 |= 1u<<j;
    }
#pragma unroll
    for (int j=0;j<32;j++){
        int t = t0 + 32 + j;
        if (s < t && adj[((size_t)(b*TT+t))*TT + s] != 0) m1 |= 1u<<j;
    }
    cm[((size_t)b*NCHUNK + k)*TT + s] = make_uint2(m0,m1);
}

// ---------------- single-launch scan: tf32 mma.sync prefill (unchanged from R15) ----------------
__global__ __launch_bounds__(SCTH, 3)
void scan_all(const float* __restrict__ xact,  const float* __restrict__ xssm,
              const float* __restrict__ xz,
              const unsigned* __restrict__ wmask, const int* __restrict__ nnz_arr,
              const float* __restrict__ invdeg,
              const float* __restrict__ Wg,    const float* __restrict__ bg,
              const float* __restrict__ Wdt,   const float* __restrict__ bdt,
              const uint2* __restrict__ cm,
              float* __restrict__ hist,        float* __restrict__ G)
{
    extern __shared__ float dsm[];
    float* lh    = dsm;                  // [CH][SCTH]
    float* stage = lh + LH_F;            // [16][STG] hist tile (tf32-rounded)
    float* sxs   = stage + STAGE2_F;     // [CH][33]
    float* sxa   = sxs + SXS_F;          // [CH][8]
    float* sxz   = sxa + SXA_F;          // [CH][8]
    __shared__ uint2 scm[16];
    __shared__ unsigned char slist[CH][CH];
    __shared__ unsigned char scnt[CH];
    __shared__ float sgate[CH];
    __shared__ float sinv[CH];

    const int NB = DI/8;                 // 192
    const int b = blockIdx.x / NB;
    const int dblk = blockIdx.x - b*NB;
    const int tid = threadIdx.x;
    const int n  = tid & 15;
    const int dl = tid >> 4;             // 0..7
    const int d  = dblk*8 + dl;
    const int c  = dblk*SCTH + tid;      // this thread's hist column
    const int wid = tid >> 5, lane = tid & 31;
    const int rA = lane >> 2;            // 0..7
    const int cA = lane & 3;             // 0..3
    const int j0 = (wid & 1)*16 + rA;
    const bool hiw = (wid >= 2);

    float wgr[16];
#pragma unroll
    for (int m=0;m<16;m++) wgr[m] = Wg[n*16 + m];
    const float bgn  = bg[n];
    const float wdtd = Wdt[d];
    const float bdtd = bdt[d];

    const float* hbase = hist + (size_t)b*TT*ND + dblk*SCTH;

    float h = 0.f;

    for (int k = 0; k < NCHUNK; k++){
        const int t0 = k*CH;

        // ---- cross-chunk prefill via tensor-core tf32 MMA ----
        float cacc[16][4];
#pragma unroll
        for (int t_=0;t_<16;t_++)
#pragma unroll
            for (int e=0;e<4;e++) cacc[t_][e]=0.f;
        const uint2* cmb = cm + ((size_t)b*NCHUNK + k)*TT;
        for (int sb = 0; sb < t0; sb += 16){
            __syncthreads();
#pragma unroll
            for (int r = 0; r < 4; r++){
                int rr = wid + r*4;
                float4 v = *(const float4*)(hbase + (size_t)(sb + rr)*ND + lane*4);
                v.x = tf32r(v.x); v.y = tf32r(v.y); v.z = tf32r(v.z); v.w = tf32r(v.w);
                *(float4*)&stage[rr*STG + lane*4] = v;
            }
            if (tid < 16) scm[tid] = cmb[sb + tid];
            __syncthreads();
#pragma unroll
            for (int ks = 0; ks < 2; ks++){
                int s0 = ks*8;
                uint2 w0 = scm[s0 + cA];
                uint2 w1 = scm[s0 + cA + 4];
                unsigned m0w = hiw ? w0.y : w0.x;
                unsigned m1w = hiw ? w1.y : w1.x;
                uint32_t a0 = ((m0w >> j0) & 1u)       ? 0x3f800000u : 0u;
                uint32_t a1 = ((m0w >> (j0+8)) & 1u)   ? 0x3f800000u : 0u;
                uint32_t a2 = ((m1w >> j0) & 1u)       ? 0x3f800000u : 0u;
                uint32_t a3 = ((m1w >> (j0+8)) & 1u)   ? 0x3f800000u : 0u;
                const float* bp0 = &stage[(s0 + cA)*STG + rA];
                const float* bp1 = &stage[(s0 + cA + 4)*STG + rA];
#pragma unroll
                for (int tile = 0; tile < 16; tile++){
                    uint32_t bf0 = __float_as_uint(bp0[tile*8]);
                    uint32_t bf1 = __float_as_uint(bp1[tile*8]);
                    asm volatile("mma.sync.aligned.m16n8k8.row.col.f32.tf32.tf32.f32 "
                        "{%0,%1,%2,%3}, {%4,%5,%6,%7}, {%8,%9}, {%0,%1,%2,%3};"
                        : "+f"(cacc[tile][0]),"+f"(cacc[tile][1]),
                          "+f"(cacc[tile][2]),"+f"(cacc[tile][3])
                        : "r"(a0),"r"(a1),"r"(a2),"r"(a3),"r"(bf0),"r"(bf1));
                }
            }
        }
#pragma unroll
        for (int tile = 0; tile < 16; tile++){
            int col = tile*8 + 2*cA;
            int row = wid*16 + rA;
            *(float2*)&lh[row*SCTH + col]     = make_float2(cacc[tile][0], cacc[tile][1]);
            *(float2*)&lh[(row+8)*SCTH + col] = make_float2(cacc[tile][2], cacc[tile][3]);
        }

        // ---- stage per-chunk metadata + step inputs ----
        if (tid < CH){
            int t = t0 + tid;
            int row = b*TT + t;
            unsigned mm0 = wmask[row*16 + 2*k];
            unsigned mm1 = wmask[row*16 + 2*k+1];
            int cidx = 0;
            while (mm0){ int p=__ffs(mm0)-1; mm0 &= mm0-1; slist[tid][cidx++] = (unsigned char)p; }
            while (mm1){ int p=__ffs(mm1)-1; mm1 &= mm1-1; slist[tid][cidx++] = (unsigned char)(p+32); }
            scnt[tid] = (unsigned char)cidx;
            sgate[tid] = (nnz_arr[t] + nnz_arr[TT + t]) > 0 ? 1.f : 0.f;
            sinv[tid] = invdeg[row];
        }
        for (int i = tid; i < CH*33; i += SCTH)
            sxs[i] = xssm[((size_t)(b*TT + t0) + i/33)*33 + (i%33)];
        for (int i = tid; i < CH*8; i += SCTH){
            int rr = i>>3, dd = i&7;
            size_t row = (size_t)(b*TT + t0 + rr);
            sxa[i] = xact[row*DI + dblk*8 + dd];
            sxz[i] = xz[row*2*DI + DI + dblk*8 + dd];
        }
        __syncthreads();

        // ---- 64 sequential steps ----
        for (int tt=0; tt<CH; tt++){
            const float* xsr = &sxs[tt*33];
            float araw = xsr[0]*wdtd + bdtd;
            float dec  = 1.f/(1.f + __expf(araw));
            float xa   = sxa[tt*8 + dl];
            float Bn   = xsr[1 + n];
            float Cn   = xsr[17 + n];
            h = h*dec + Bn*xa;

            float g = lh[tt*SCTH + tid];
            int nz = scnt[tt];
            const unsigned char* lp = &slist[tt][0];
            int j = 0;
            for (; j+4 <= nz; j += 4){
                float v0 = lh[lp[j]  *SCTH + tid];
                float v1 = lh[lp[j+1]*SCTH + tid];
                float v2 = lh[lp[j+2]*SCTH + tid];
                float v3 = lh[lp[j+3]*SCTH + tid];
                g += (v0+v1) + (v2+v3);
            }
            for (; j < nz; j++) g += lh[lp[j]*SCTH + tid];
            g *= sinv[tt];

            float a = bgn;
#pragma unroll
            for (int m=0;m<16;m++)
                a += wgr[m] * __shfl_sync(0xffffffffu, g, m, 16);
            float upd = 0.1f * a / (1.f + __expf(-a));
            h += sgate[tt] * upd;

            lh[tt*SCTH + tid] = h;

            float y = h * Cn;
#pragma unroll
            for (int o=8; o; o>>=1) y += __shfl_xor_sync(0xffffffffu, y, o, 16);
            if (n == 0){
                float zz = sxz[tt*8 + dl];
                G[((size_t)(b*TT + t0 + tt))*DI + d] = y * (zz / (1.f + __expf(-zz)));
            }
        }

        // ---- flush chunk hist ----
#pragma unroll 4
        for (int tt=0; tt<CH; tt++)
            hist[((size_t)(b*TT + t0 + tt))*ND + c] = lh[tt*SCTH + tid];
    }
}

// ---------------- launch ----------------
extern "C" void kernel_launch(void* const* d_in, const int* in_sizes, int n_in,
                              void* d_out, int out_size)
{
    (void)in_sizes; (void)n_in; (void)out_size;
    const float* x        = (const float*)d_in[0];
    const int*   adj      = (const int*)  d_in[1];
    const float* ln_scale = (const float*)d_in[2];
    const float* ln_bias  = (const float*)d_in[3];
    const float* W_in     = (const float*)d_in[4];
    const float* conv_w   = (const float*)d_in[5];
    const float* conv_b   = (const float*)d_in[6];
    const float* W_x      = (const float*)d_in[7];
    const float* W_dt     = (const float*)d_in[8];
    const float* b_dt     = (const float*)d_in[9];
    const float* W_g      = (const float*)d_in[10];
    const float* b_g      = (const float*)d_in[11];
    const float* W_out    = (const float*)d_in[12];
    float* out = (float*)d_out;

    float *p_xn, *p_xz, *p_xact, *p_wc, *p_xssm, *p_hist, *p_G,
          *p_invdeg, *p_part, *p_opart;
    unsigned *p_wmask; uint2 *p_cm; int *p_nnz;
    cudaGetSymbolAddress((void**)&p_xn,    g_xn);
    cudaGetSymbolAddress((void**)&p_xz,    g_xz);
    cudaGetSymbolAddress((void**)&p_xact,  g_xact);
    cudaGetSymbolAddress((void**)&p_wc,    g_wc);
    cudaGetSymbolAddress((void**)&p_xssm,  g_xssm);
    cudaGetSymbolAddress((void**)&p_hist,  g_hist);
    cudaGetSymbolAddress((void**)&p_G,     g_G);
    cudaGetSymbolAddress((void**)&p_part,  g_part);
    cudaGetSymbolAddress((void**)&p_opart, g_opart);
    cudaGetSymbolAddress((void**)&p_wmask, g_wmask);
    cudaGetSymbolAddress((void**)&p_cm,    g_cm);
    cudaGetSymbolAddress((void**)&p_nnz,   g_nnz);
    cudaGetSymbolAddress((void**)&p_invdeg,g_invdeg);

    cudaFuncSetAttribute(scan_all, cudaFuncAttributeMaxDynamicSharedMemorySize, SCAN_DYN);

    // ---- position 4 = conv GEMM (profiled) ----
    // 1. layernorm
    ln_kernel<<<NROW, 256>>>(x, ln_scale, ln_bias, p_xn);
    // 2. xz = xn @ W_in^T   (tf32 mma)
    gemmtf<0><<<dim3(2*DI/128, NROW/128, 1), 256>>>(p_xn, DM, W_in, DM, p_xz, 2*DI, 0, DM);
    // 3. conv weight re-layout (coalesced)
    wct_kernel<<<DI, 256>>>(conv_w, p_wc);
    // 4. conv as GEMM with fused pad (tf32 mma, split 3)   <-- profiled
    gemmtf<1><<<dim3(DI/128, NROW/128, 3), 256>>>(p_xz, 0, p_wc, KW, p_part, DI,
                                                  (size_t)NROW*DI, KW/3);
    // 5. fused combine+silu+xssm
    actssm_kernel<<<NROW, 256>>>(p_part, conv_b, W_x, p_xact, p_xssm);
    // 6. adjacency bitmasks
    adj_kernel<<<NROW, 32>>>(adj, p_wmask, p_nnz, p_invdeg);
    // 7. transposed chunk masks
    cmt_kernel<<<dim3(NCHUNK, BATCH), TT>>>(adj, p_cm);
    // 8. single-launch scan (tf32 mma prefill)
    scan_all<<<BATCH*(DI/8), SCTH, SCAN_DYN>>>(
        p_xact, p_xssm, p_xz, p_wmask, p_nnz, p_invdeg,
        W_g, b_g, W_dt, b_dt, p_cm, p_hist, p_G);
    // 9. out = G @ W_out^T (tf32 mma, split 6)
    gemmtf<0><<<dim3(DM/128, NROW/128, 6), 256>>>(p_G, DI, W_out, DI, p_opart, DM,
                                                  (size_t)NROW*DM, DI/6);
    // 10. combine out partials + residual
    fixout_kernel<<<(NROW*DM/4 + 255)/256, 256>>>(p_opart, x, out);
}

// round 17
// speedup vs baseline: 1.5694x; 1.0331x over previous
#include <cuda_runtime.h>
#include <cstdint>

#define BATCH 2
#define TT 512
#define DM 768
#define DI 1536
#define DS 16
#define NROW (BATCH*TT)          // 1024
#define KCONV 4
#define KW (KCONV*DI)            // 6144
#define ND (DS*DI)               // 24576
#define CH 64
#define NCHUNK (TT/CH)           // 8
#define SCTH 128                 // scan threads: 8 dl x 16 n; 128 hist columns/block

typedef unsigned long long u64;
static __device__ __forceinline__ float tf32r(float v){
    uint32_t u; asm("cvt.rna.tf32.f32 %0, %1;" : "=r"(u) : "f"(v));
    return __uint_as_float(u);
}
static __device__ __forceinline__ void mma_tf32(float* c, uint32_t a0, uint32_t a1,
                                                uint32_t a2, uint32_t a3,
                                                uint32_t b0, uint32_t b1){
    asm volatile("mma.sync.aligned.m16n8k8.row.col.f32.tf32.tf32.f32 "
        "{%0,%1,%2,%3}, {%4,%5,%6,%7}, {%8,%9}, {%0,%1,%2,%3};"
        : "+f"(c[0]),"+f"(c[1]),"+f"(c[2]),"+f"(c[3])
        : "r"(a0),"r"(a1),"r"(a2),"r"(a3),"r"(b0),"r"(b1));
}

// scan dynamic smem (floats)
#define LH_F     (CH*SCTH)       // 8192
#define STG      136             // stage row stride (conflict-free mma b-loads)
#define STAGE2_F (16*STG)        // 2176
#define SXS_F    (CH*33)         // 2112
#define SXA_F    (CH*8)          // 512
#define SXZ_F    (CH*8)          // 512
#define SCAN_DYN ((LH_F+STAGE2_F+SXS_F+SXA_F+SXZ_F)*sizeof(float))   // 54016 B

// GEMM paired-fragment smem geometry (float2 units)
#define KHS 529                  // kh-group stride: 4 p-rows * 132 + 1 pad
#define ABUF 1058                // per-operand per-buffer float2 count (2 kh groups)

// ---------------- scratch ----------------
__device__ __align__(16) float g_xn   [NROW*DM];
__device__ __align__(16) float g_xz   [NROW*2*DI];
__device__ __align__(16) float g_xact [NROW*DI];
__device__ __align__(16) float g_wc   [DI*KW];
__device__ __align__(16) float g_xssm [NROW*33];
__device__ __align__(16) float g_hist [(size_t)BATCH*TT*ND];   // block-local cols
__device__ __align__(16) float g_G    [NROW*DI];
__device__ __align__(16) float g_part [(size_t)3*NROW*DI];
__device__ __align__(16) float g_opart[(size_t)6*NROW*DM];
__device__ __align__(16) unsigned g_wmask[NROW*16];
__device__ __align__(16) uint2 g_cm[BATCH*NCHUNK*TT];
__device__ int   g_nnz[NROW];
__device__ float g_invdeg[NROW];

__device__ __forceinline__ float siluf(float v){ return v / (1.f + __expf(-v)); }

// ---------------- layernorm ----------------
__global__ void ln_kernel(const float* __restrict__ x,
                          const float* __restrict__ sc,
                          const float* __restrict__ bi,
                          float* __restrict__ out)
{
    int m = blockIdx.x;
    const float* xr = x + (size_t)m*DM;
    int tid = threadIdx.x;
    float v[3]; float s=0.f, sq=0.f;
#pragma unroll
    for (int q=0;q<3;q++){ v[q]=xr[tid+q*256]; s+=v[q]; sq+=v[q]*v[q]; }
#pragma unroll
    for (int o=16;o;o>>=1){ s+=__shfl_down_sync(~0u,s,o); sq+=__shfl_down_sync(~0u,sq,o); }
    __shared__ float sh0[8], sh1[8];
    int lane=tid&31, w=tid>>5;
    if (lane==0){ sh0[w]=s; sh1[w]=sq; }
    __syncthreads();
    __shared__ float smu, srs;
    if (tid==0){
        float S=0.f,SQ=0.f;
#pragma unroll
        for (int i=0;i<8;i++){ S+=sh0[i]; SQ+=sh1[i]; }
        float mu=S/(float)DM;
        float var=SQ/(float)DM - mu*mu;
        smu=mu; srs=rsqrtf(var+1e-5f);
    }
    __syncthreads();
    float mu=smu, rs=srs;
#pragma unroll
    for (int q=0;q<3;q++){
        int k=tid+q*256;
        out[(size_t)m*DM+k] = (v[q]-mu)*rs*sc[k]+bi[k];
    }
}

// ===== 128x128x16 single-pass tf32 mma GEMM, paired-fragment float2 smem =====
// 256 threads (8 warps, 4M x 2N). SMEM stores float2(val[k], val[k+4]) so every
// mma operand pair is ONE LDS.64 (conflict-free: bank = 8*cA + 2*rA).
template<int CONV>
__global__ __launch_bounds__(256, 2)
void gemmtf(const float* __restrict__ A, int lda,
            const float* __restrict__ B, int ldb,
            float* __restrict__ Cbase, int ldc, size_t cstride,
            int Klen)
{
    __shared__ float2 S2[2][2*ABUF];      // [buf][A:0..ABUF) B:[ABUF..2*ABUF)]
    const int tid = threadIdx.x;
    const int m0 = blockIdx.y*128, n0 = blockIdx.x*128;
    const int kbeg = blockIdx.z*Klen;
    float* C = Cbase + (size_t)blockIdx.z*cstride;
    const int lane = tid & 31, wid = tid >> 5;
    const int rA = lane >> 2, cA = lane & 3;
    const int wm = wid >> 1, wn = wid & 1;   // warp tile: 32M x 64N
    // loader: thread handles one row (ln), k-group kh (8 cols kh*8..kh*8+7)
    const int ln = tid & 127, khl = tid >> 7;
    const int c8 = khl*8;

    // conv incremental window state (single row)
    int ccur = 0, ts = 0;
    long long ao = 0;
    size_t aoff = 0;
    {
        int gm = m0 + ln;
        if (CONV){
            int cb = gm>>9, ct = gm&511;
            int tau0 = (kbeg + c8) / 1536;
            int ci0  = kbeg + c8 - tau0*1536;
            ccur = ci0;
            ts = ct + tau0 - 3;
            ao = ((long long)(cb*TT) + ts)*(2*DI) + ci0;
        } else {
            aoff = (size_t)gm*lda + kbeg + c8;
        }
    }
    const size_t boff = (size_t)(n0 + ln)*ldb + kbeg + c8;

    float cacc[2][8][4];
#pragma unroll
    for (int mt=0;mt<2;mt++)
#pragma unroll
        for (int nt=0;nt<8;nt++)
#pragma unroll
            for (int e=0;e<4;e++) cacc[mt][nt][e]=0.f;

    float4 ra0, ra1, rb0, rb1;
    int koff = 0;

#define LOAD_ADV() do { \
    if (CONV){ \
        ra0 = make_float4(0.f,0.f,0.f,0.f); ra1 = ra0; \
        if (ts >= 0){ \
            ra0 = *(const float4*)(A + ao); \
            ra1 = *(const float4*)(A + ao + 4); \
        } \
    } else { \
        ra0 = *(const float4*)(A + aoff + koff); \
        ra1 = *(const float4*)(A + aoff + koff + 4); \
    } \
    rb0 = *(const float4*)(B + boff + koff); \
    rb1 = *(const float4*)(B + boff + koff + 4); \
    koff += 16; \
    if (CONV){ \
        ccur += 16; \
        long long adv = 16; \
        if (ccur >= 1536){ ccur -= 1536; adv = 16 + (2*DI - 1536); ts++; } \
        ao += adv; \
    } \
} while(0)

// pairs: (v[p], v[p+4]) for p=0..3; v = {ra0.xyzw, ra1.xyzw}
#define STORE_TILE(BUF_) do { \
    float2* pa = &S2[BUF_][khl*KHS + ln]; \
    pa[0*132] = make_float2(tf32r(ra0.x), tf32r(ra1.x)); \
    pa[1*132] = make_float2(tf32r(ra0.y), tf32r(ra1.y)); \
    pa[2*132] = make_float2(tf32r(ra0.z), tf32r(ra1.z)); \
    pa[3*132] = make_float2(tf32r(ra0.w), tf32r(ra1.w)); \
    float2* pb = &S2[BUF_][ABUF + khl*KHS + ln]; \
    pb[0*132] = make_float2(tf32r(rb0.x), tf32r(rb1.x)); \
    pb[1*132] = make_float2(tf32r(rb0.y), tf32r(rb1.y)); \
    pb[2*132] = make_float2(tf32r(rb0.z), tf32r(rb1.z)); \
    pb[3*132] = make_float2(tf32r(rb0.w), tf32r(rb1.w)); \
} while(0)

    LOAD_ADV();
    STORE_TILE(0);
    __syncthreads();

    const int KT = Klen/16;
    int cur = 0;
    for (int kt=0; kt<KT; kt++){
        if (kt+1 < KT) LOAD_ADV();
#pragma unroll
        for (int ksh=0; ksh<2; ksh++){
            const float2* A2 = &S2[cur][ksh*KHS + cA*132];
            const float2* B2 = &S2[cur][ABUF + ksh*KHS + cA*132];
            // A fragments: one LDS.64 per (mt, row-half)
            uint32_t afr[2][4];
#pragma unroll
            for (int mt=0;mt<2;mt++){
                int base = wm*32 + mt*16;
                float2 fa = A2[base + rA];
                float2 fb = A2[base + rA + 8];
                afr[mt][0] = __float_as_uint(fa.x);   // A[m=base+rA][k=cA]
                afr[mt][1] = __float_as_uint(fb.x);   // A[m=base+rA+8][k=cA]
                afr[mt][2] = __float_as_uint(fa.y);   // A[m=base+rA][k=cA+4]
                afr[mt][3] = __float_as_uint(fb.y);   // A[m=base+rA+8][k=cA+4]
            }
#pragma unroll
            for (int nt=0;nt<8;nt++){
                int col = wn*64 + nt*8 + rA;
                float2 fb = B2[col];                  // (B[k=cA][n], B[k=cA+4][n])
                uint32_t b0 = __float_as_uint(fb.x);
                uint32_t b1 = __float_as_uint(fb.y);
                mma_tf32(cacc[0][nt], afr[0][0],afr[0][1],afr[0][2],afr[0][3], b0,b1);
                mma_tf32(cacc[1][nt], afr[1][0],afr[1][1],afr[1][2],afr[1][3], b0,b1);
            }
        }
        if (kt+1 < KT){
            int nxt = cur^1;
            STORE_TILE(nxt);
            __syncthreads();
            cur = nxt;
        }
    }

    // epilogue: validated fragment layout
#pragma unroll
    for (int mt=0;mt<2;mt++){
        int gm = m0 + wm*32 + mt*16 + rA;
#pragma unroll
        for (int nt=0;nt<8;nt++){
            int gn = n0 + wn*64 + nt*8 + 2*cA;
            *(float2*)(C + (size_t)gm*ldc + gn)     = make_float2(cacc[mt][nt][0], cacc[mt][nt][1]);
            *(float2*)(C + (size_t)(gm+8)*ldc + gn) = make_float2(cacc[mt][nt][2], cacc[mt][nt][3]);
        }
    }
#undef LOAD_ADV
#undef STORE_TILE
}

// ---------------- fused: conv partials + bias + silu -> xact, and x_ssm = xact @ W_x^T ----------------
__global__ void actssm_kernel(const float* __restrict__ part,
                              const float* __restrict__ cb,
                              const float* __restrict__ Wx,
                              float* __restrict__ xact,
                              float* __restrict__ xssm)
{
    int m = blockIdx.x;
    float accv[33];
#pragma unroll
    for (int n=0;n<33;n++) accv[n]=0.f;
    for (int k = threadIdx.x; k < DI; k += 256){
        size_t i = (size_t)m*DI + k;
        float v = part[i] + part[i + (size_t)NROW*DI] + part[i + 2*(size_t)NROW*DI] + cb[k];
        float xv = siluf(v);
        xact[i] = xv;
#pragma unroll
        for (int n=0;n<33;n++) accv[n] += xv * Wx[n*DI + k];
    }
    int lane=threadIdx.x&31, w=threadIdx.x>>5;
#pragma unroll
    for (int n=0;n<33;n++)
#pragma unroll
        for (int o=16;o;o>>=1) accv[n] += __shfl_down_sync(~0u, accv[n], o);
    __shared__ float sred[8][33];
    if (lane==0)
#pragma unroll
        for (int n=0;n<33;n++) sred[w][n]=accv[n];
    __syncthreads();
    if (threadIdx.x < 33){
        float s=0.f;
#pragma unroll
        for (int q=0;q<8;q++) s += sred[q][threadIdx.x];
        xssm[(size_t)m*33 + threadIdx.x] = s;
    }
}

// ---------------- combine out partials (6) + residual ----------------
__global__ void fixout_kernel(const float* __restrict__ opart,
                              const float* __restrict__ x,
                              float* __restrict__ out)
{
    int i = blockIdx.x*256 + threadIdx.x;
    if (i >= NROW*DM/4) return;
    float4 s = ((const float4*)x)[i];
#pragma unroll
    for (int p=0;p<6;p++){
        const float4 v = ((const float4*)opart)[i + (size_t)p*(NROW*DM/4)];
        s.x+=v.x; s.y+=v.y; s.z+=v.z; s.w+=v.w;
    }
    ((float4*)out)[i] = s;
}

// ---------------- conv weight re-layout, fully coalesced ----------------
__global__ __launch_bounds__(256)
void wct_kernel(const float* __restrict__ cw, float* __restrict__ wc)
{
    int o = blockIdx.x;
    const float4* src = (const float4*)(cw + (size_t)o*DI*KCONV);
    float* dst = wc + (size_t)o*KW;
#pragma unroll
    for (int r = 0; r < DI/256; r++){
        int i = threadIdx.x + r*256;
        float4 v = src[i];
        dst[0*DI + i] = v.x;
        dst[1*DI + i] = v.y;
        dst[2*DI + i] = v.z;
        dst[3*DI + i] = v.w;
    }
}

// ---------------- adjacency bitmasks ----------------
__global__ void adj_kernel(const int* __restrict__ adj,
                           unsigned* __restrict__ wmask,
                           int* __restrict__ nnz,
                           float* __restrict__ invdeg)
{
    int rowid = blockIdx.x;
    int t = rowid & (TT-1);
    int lane = threadIdx.x;
    const int* arow = adj + (size_t)rowid*TT;
    int cnt = 0;
    for (int w = 0; w < 16; w++){
        int s = w*32 + lane;
        bool nz = (s < t) && (arow[s] != 0);
        unsigned m = __ballot_sync(~0u, nz);
        if (lane==0) wmask[rowid*16 + w] = m;
        cnt += __popc(m);
    }
    if (lane==0){
        nnz[rowid] = cnt;
        invdeg[rowid] = 1.0f / (float)(cnt < 1 ? 1 : cnt);
    }
}

// ---------------- transposed chunk masks ----------------
__global__ void cmt_kernel(const int* __restrict__ adj, uint2* __restrict__ cm)
{
    int s = threadIdx.x;
    int k = blockIdx.x;
    int b = blockIdx.y;
    int t0 = k*CH;
    unsigned m0=0, m1=0;
#pragma unroll
    for (int j=0;j<32;j++){
        int t = t0 + j;
        if (s < t && adj[((size_t)(b*TT+t))*TT + s] != 0) m0 |= 1u<<j;
    }
#pragma unroll
    for (int j=0;j<32;j++){
        int t = t0 + 32 + j;
        if (s < t && adj[((size_t)(b*TT+t))*TT + s] != 0) m1 |= 1u<<j;
    }
    cm[((size_t)b*NCHUNK + k)*TT + s] = make_uint2(m0,m1);
}

// ---------------- single-launch scan: tf32 mma.sync prefill (unchanged from R16) ----------------
__global__ __launch_bounds__(SCTH, 3)
void scan_all(const float* __restrict__ xact,  const float* __restrict__ xssm,
              const float* __restrict__ xz,
              const unsigned* __restrict__ wmask, const int* __restrict__ nnz_arr,
              const float* __restrict__ invdeg,
              const float* __restrict__ Wg,    const float* __restrict__ bg,
              const float* __restrict__ Wdt,   const float* __restrict__ bdt,
              const uint2* __restrict__ cm,
              float* __restrict__ hist,        float* __restrict__ G)
{
    extern __shared__ float dsm[];
    float* lh    = dsm;                  // [CH][SCTH]
    float* stage = lh + LH_F;            // [16][STG] hist tile (tf32-rounded)
    float* sxs   = stage + STAGE2_F;     // [CH][33]
    float* sxa   = sxs + SXS_F;          // [CH][8]
    float* sxz   = sxa + SXA_F;          // [CH][8]
    __shared__ uint2 scm[16];
    __shared__ unsigned char slist[CH][CH];
    __shared__ unsigned char scnt[CH];
    __shared__ float sgate[CH];
    __shared__ float sinv[CH];

    const int NB = DI/8;                 // 192
    const int b = blockIdx.x / NB;
    const int dblk = blockIdx.x - b*NB;
    const int tid = threadIdx.x;
    const int n  = tid & 15;
    const int dl = tid >> 4;             // 0..7
    const int d  = dblk*8 + dl;
    const int c  = dblk*SCTH + tid;      // this thread's hist column
    const int wid = tid >> 5, lane = tid & 31;
    const int rA = lane >> 2;            // 0..7
    const int cA = lane & 3;             // 0..3
    const int j0 = (wid & 1)*16 + rA;
    const bool hiw = (wid >= 2);

    float wgr[16];
#pragma unroll
    for (int m=0;m<16;m++) wgr[m] = Wg[n*16 + m];
    const float bgn  = bg[n];
    const float wdtd = Wdt[d];
    const float bdtd = bdt[d];

    const float* hbase = hist + (size_t)b*TT*ND + dblk*SCTH;

    float h = 0.f;

    for (int k = 0; k < NCHUNK; k++){
        const int t0 = k*CH;

        // ---- cross-chunk prefill via tensor-core tf32 MMA ----
        float cacc[16][4];
#pragma unroll
        for (int t_=0;t_<16;t_++)
#pragma unroll
            for (int e=0;e<4;e++) cacc[t_][e]=0.f;
        const uint2* cmb = cm + ((size_t)b*NCHUNK + k)*TT;
        for (int sb = 0; sb < t0; sb += 16){
            __syncthreads();
#pragma unroll
            for (int r = 0; r < 4; r++){
                int rr = wid + r*4;
                float4 v = *(const float4*)(hbase + (size_t)(sb + rr)*ND + lane*4);
                v.x = tf32r(v.x); v.y = tf32r(v.y); v.z = tf32r(v.z); v.w = tf32r(v.w);
                *(float4*)&stage[rr*STG + lane*4] = v;
            }
            if (tid < 16) scm[tid] = cmb[sb + tid];
            __syncthreads();
#pragma unroll
            for (int ks = 0; ks < 2; ks++){
                int s0 = ks*8;
                uint2 w0 = scm[s0 + cA];
                uint2 w1 = scm[s0 + cA + 4];
                unsigned m0w = hiw ? w0.y : w0.x;
                unsigned m1w = hiw ? w1.y : w1.x;
                uint32_t a0 = ((m0w >> j0) & 1u)       ? 0x3f800000u : 0u;
                uint32_t a1 = ((m0w >> (j0+8)) & 1u)   ? 0x3f800000u : 0u;
                uint32_t a2 = ((m1w >> j0) & 1u)       ? 0x3f800000u : 0u;
                uint32_t a3 = ((m1w >> (j0+8)) & 1u)   ? 0x3f800000u : 0u;
                const float* bp0 = &stage[(s0 + cA)*STG + rA];
                const float* bp1 = &stage[(s0 + cA + 4)*STG + rA];
#pragma unroll
                for (int tile = 0; tile < 16; tile++){
                    uint32_t bf0 = __float_as_uint(bp0[tile*8]);
                    uint32_t bf1 = __float_as_uint(bp1[tile*8]);
                    asm volatile("mma.sync.aligned.m16n8k8.row.col.f32.tf32.tf32.f32 "
                        "{%0,%1,%2,%3}, {%4,%5,%6,%7}, {%8,%9}, {%0,%1,%2,%3};"
                        : "+f"(cacc[tile][0]),"+f"(cacc[tile][1]),
                          "+f"(cacc[tile][2]),"+f"(cacc[tile][3])
                        : "r"(a0),"r"(a1),"r"(a2),"r"(a3),"r"(bf0),"r"(bf1));
                }
            }
        }
#pragma unroll
        for (int tile = 0; tile < 16; tile++){
            int col = tile*8 + 2*cA;
            int row = wid*16 + rA;
            *(float2*)&lh[row*SCTH + col]     = make_float2(cacc[tile][0], cacc[tile][1]);
            *(float2*)&lh[(row+8)*SCTH + col] = make_float2(cacc[tile][2], cacc[tile][3]);
        }

        // ---- stage per-chunk metadata + step inputs ----
        if (tid < CH){
            int t = t0 + tid;
            int row = b*TT + t;
            unsigned mm0 = wmask[row*16 + 2*k];
            unsigned mm1 = wmask[row*16 + 2*k+1];
            int cidx = 0;
            while (mm0){ int p=__ffs(mm0)-1; mm0 &= mm0-1; slist[tid][cidx++] = (unsigned char)p; }
            while (mm1){ int p=__ffs(mm1)-1; mm1 &= mm1-1; slist[tid][cidx++] = (unsigned char)(p+32); }
            scnt[tid] = (unsigned char)cidx;
            sgate[tid] = (nnz_arr[t] + nnz_arr[TT + t]) > 0 ? 1.f : 0.f;
            sinv[tid] = invdeg[row];
        }
        for (int i = tid; i < CH*33; i += SCTH)
            sxs[i] = xssm[((size_t)(b*TT + t0) + i/33)*33 + (i%33)];
        for (int i = tid; i < CH*8; i += SCTH){
            int rr = i>>3, dd = i&7;
            size_t row = (size_t)(b*TT + t0 + rr);
            sxa[i] = xact[row*DI + dblk*8 + dd];
            sxz[i] = xz[row*2*DI + DI + dblk*8 + dd];
        }
        __syncthreads();

        // ---- 64 sequential steps ----
        for (int tt=0; tt<CH; tt++){
            const float* xsr = &sxs[tt*33];
            float araw = xsr[0]*wdtd + bdtd;
            float dec  = 1.f/(1.f + __expf(araw));
            float xa   = sxa[tt*8 + dl];
            float Bn   = xsr[1 + n];
            float Cn   = xsr[17 + n];
            h = h*dec + Bn*xa;

            float g = lh[tt*SCTH + tid];
            int nz = scnt[tt];
            const unsigned char* lp = &slist[tt][0];
            int j = 0;
            for (; j+4 <= nz; j += 4){
                float v0 = lh[lp[j]  *SCTH + tid];
                float v1 = lh[lp[j+1]*SCTH + tid];
                float v2 = lh[lp[j+2]*SCTH + tid];
                float v3 = lh[lp[j+3]*SCTH + tid];
                g += (v0+v1) + (v2+v3);
            }
            for (; j < nz; j++) g += lh[lp[j]*SCTH + tid];
            g *= sinv[tt];

            float a = bgn;
#pragma unroll
            for (int m=0;m<16;m++)
                a += wgr[m] * __shfl_sync(0xffffffffu, g, m, 16);
            float upd = 0.1f * a / (1.f + __expf(-a));
            h += sgate[tt] * upd;

            lh[tt*SCTH + tid] = h;

            float y = h * Cn;
#pragma unroll
            for (int o=8; o; o>>=1) y += __shfl_xor_sync(0xffffffffu, y, o, 16);
            if (n == 0){
                float zz = sxz[tt*8 + dl];
                G[((size_t)(b*TT + t0 + tt))*DI + d] = y * (zz / (1.f + __expf(-zz)));
            }
        }

        // ---- flush chunk hist ----
#pragma unroll 4
        for (int tt=0; tt<CH; tt++)
            hist[((size_t)(b*TT + t0 + tt))*ND + c] = lh[tt*SCTH + tid];
    }
}

// ---------------- launch ----------------
extern "C" void kernel_launch(void* const* d_in, const int* in_sizes, int n_in,
                              void* d_out, int out_size)
{
    (void)in_sizes; (void)n_in; (void)out_size;
    const float* x        = (const float*)d_in[0];
    const int*   adj      = (const int*)  d_in[1];
    const float* ln_scale = (const float*)d_in[2];
    const float* ln_bias  = (const float*)d_in[3];
    const float* W_in     = (const float*)d_in[4];
    const float* conv_w   = (const float*)d_in[5];
    const float* conv_b   = (const float*)d_in[6];
    const float* W_x      = (const float*)d_in[7];
    const float* W_dt     = (const float*)d_in[8];
    const float* b_dt     = (const float*)d_in[9];
    const float* W_g      = (const float*)d_in[10];
    const float* b_g      = (const float*)d_in[11];
    const float* W_out    = (const float*)d_in[12];
    float* out = (float*)d_out;

    float *p_xn, *p_xz, *p_xact, *p_wc, *p_xssm, *p_hist, *p_G,
          *p_invdeg, *p_part, *p_opart;
    unsigned *p_wmask; uint2 *p_cm; int *p_nnz;
    cudaGetSymbolAddress((void**)&p_xn,    g_xn);
    cudaGetSymbolAddress((void**)&p_xz,    g_xz);
    cudaGetSymbolAddress((void**)&p_xact,  g_xact);
    cudaGetSymbolAddress((void**)&p_wc,    g_wc);
    cudaGetSymbolAddress((void**)&p_xssm,  g_xssm);
    cudaGetSymbolAddress((void**)&p_hist,  g_hist);
    cudaGetSymbolAddress((void**)&p_G,     g_G);
    cudaGetSymbolAddress((void**)&p_part,  g_part);
    cudaGetSymbolAddress((void**)&p_opart, g_opart);
    cudaGetSymbolAddress((void**)&p_wmask, g_wmask);
    cudaGetSymbolAddress((void**)&p_cm,    g_cm);
    cudaGetSymbolAddress((void**)&p_nnz,   g_nnz);
    cudaGetSymbolAddress((void**)&p_invdeg,g_invdeg);

    cudaFuncSetAttribute(scan_all, cudaFuncAttributeMaxDynamicSharedMemorySize, SCAN_DYN);

    // ---- position 4 = conv GEMM (profiled) ----
    // 1. layernorm
    ln_kernel<<<NROW, 256>>>(x, ln_scale, ln_bias, p_xn);
    // 2. xz = xn @ W_in^T   (tf32 mma)
    gemmtf<0><<<dim3(2*DI/128, NROW/128, 1), 256>>>(p_xn, DM, W_in, DM, p_xz, 2*DI, 0, DM);
    // 3. conv weight re-layout (coalesced)
    wct_kernel<<<DI, 256>>>(conv_w, p_wc);
    // 4. conv as GEMM with fused pad (tf32 mma, split 3)   <-- profiled
    gemmtf<1><<<dim3(DI/128, NROW/128, 3), 256>>>(p_xz, 0, p_wc, KW, p_part, DI,
                                                  (size_t)NROW*DI, KW/3);
    // 5. fused combine+silu+xssm
    actssm_kernel<<<NROW, 256>>>(p_part, conv_b, W_x, p_xact, p_xssm);
    // 6. adjacency bitmasks
    adj_kernel<<<NROW, 32>>>(adj, p_wmask, p_nnz, p_invdeg);
    // 7. transposed chunk masks
    cmt_kernel<<<dim3(NCHUNK, BATCH), TT>>>(adj, p_cm);
    // 8. single-launch scan (tf32 mma prefill)
    scan_all<<<BATCH*(DI/8), SCTH, SCAN_DYN>>>(
        p_xact, p_xssm, p_xz, p_wmask, p_nnz, p_invdeg,
        W_g, b_g, W_dt, b_dt, p_cm, p_hist, p_G);
    // 9. out = G @ W_out^T (tf32 mma, split 6)
    gemmtf<0><<<dim3(DM/128, NROW/128, 6), 256>>>(p_G, DI, W_out, DI, p_opart, DM,
                                                  (size_t)NROW*DM, DI/6);
    // 10. combine out partials + residual
    fixout_kernel<<<(NROW*DM/4 + 255)/256, 256>>>(p_opart, x, out);
}